// round 6
// baseline (speedup 1.0000x reference)
#include <cuda_runtime.h>

typedef unsigned long long u64;
typedef unsigned int u32;

#define SEQ   2048
#define DM    1024
#define NH    8
#define HD    128
#define NB    2
#define NROWS (NB*NH*SEQ)
#define TOPK  32

__device__ int   g_topk[NROWS*TOPK];
__device__ float g_m[NROWS];
__device__ float g_z[NROWS];

__device__ __forceinline__ u32 fkey(float f){
    u32 b = __float_as_uint(f);
    return (b & 0x80000000u) ? ~b : (b | 0x80000000u);
}

// ---------------------------------------------------------------------------
// Kernel 1: exact top-32 of each attention_weight row (value desc, index asc).
// One 256-thread block per row; 8 values/thread in registers; 32 rounds of
// block-wide argmax over 64-bit keys.
// ---------------------------------------------------------------------------
__global__ __launch_bounds__(256) void topk_kernel(const float* __restrict__ aw){
    const int row = blockIdx.x;
    const float* __restrict__ ar = aw + (size_t)row * SEQ;
    const int t = threadIdx.x, lane = t & 31, wid = t >> 5;
    u64 kv[8];
#pragma unroll
    for (int j = 0; j < 8; ++j){
        int idx = t + j*256;
        float v = ar[idx];
        kv[j] = ((u64)fkey(v) << 32) | (u32)(SEQ-1-idx);
    }
    __shared__ u64 swm[8];
    __shared__ u64 swin;
    int* outp = g_topk + (size_t)row * TOPK;
    for (int r = 0; r < TOPK; ++r){
        u64 loc = 0;
#pragma unroll
        for (int j = 0; j < 8; ++j) loc = kv[j] > loc ? kv[j] : loc;
#pragma unroll
        for (int o = 16; o; o >>= 1){
            u64 w = __shfl_xor_sync(0xffffffffu, loc, o);
            loc = w > loc ? w : loc;
        }
        if (lane == 0) swm[wid] = loc;
        __syncthreads();
        if (t == 0){
            u64 w = swm[0];
#pragma unroll
            for (int i = 1; i < 8; ++i) w = swm[i] > w ? swm[i] : w;
            swin = w;
            outp[r] = (SEQ-1) - (int)(u32)(w & 0xffffffffull);
        }
        __syncthreads();
        u64 w = swin;
#pragma unroll
        for (int j = 0; j < 8; ++j) if (kv[j] == w) kv[j] = 0;
    }
}

// ---------------------------------------------------------------------------
// Kernel 2: per-row (m, Z) of full softmax via FFMA2 (fp32x2) tiled QK^T.
// Block = (head-batch hb, 128-query tile). K looped in 16 tiles of 128 keys.
// Smem: Qt = Q transposed [smem_dim][130 f32] (query pairs adjacent, +2 pad),
//       Kd = K duplicated  [key][128 u64]  ((k,k) pairs),
// with a consistent dim permutation sd = (gd&3)*32 + (gd>>2) applied to BOTH
// (dots are order-invariant) so all stores/loads are conflict-free.
// Thread (g1=t>>4, g2=t&15): 8 keys (g1*8+i) x 4 query-pairs (2*(16p+g2)+e).
// ---------------------------------------------------------------------------
__device__ __forceinline__ void ffma2(u64 &d, u64 a, u64 b){
    asm("fma.rn.f32x2 %0, %1, %2, %0;" : "+l"(d) : "l"(a), "l"(b));
}

#define QT_U64 (65*128)
#define KD_U64 (128*128)
#define SMEM2_BYTES ((QT_U64 + KD_U64)*8 + 8*128*8)

__global__ __launch_bounds__(256,1) void mz_kernel(const float* __restrict__ q,
                                                   const float* __restrict__ k){
    extern __shared__ u64 sm[];
    u64*    Qt  = sm;                       // f32 view: [sd][130]
    float*  Qtf = (float*)Qt;
    u64*    Kd  = sm + QT_U64;              // [key][128] duplicated u64
    float2* mz  = (float2*)(sm + QT_U64 + KD_U64);   // [8 warps][128 queries]

    const int t  = threadIdx.x;
    const int hb = blockIdx.x >> 4;
    const int qt = blockIdx.x & 15;
    const int b  = hb >> 3, h = hb & 7;
    const float* Qg = q + ((size_t)(b*SEQ + qt*128))*DM + h*HD;
    const float* Kg = k + (size_t)b*SEQ*DM + h*HD;

    // Load + transpose Q tile (once). Write conflicts: 2-way (acceptable, once).
#pragma unroll
    for (int mm = 0; mm < 16; ++mm){
        int f4 = mm*256 + t;
        int qrow = f4 >> 5, c = f4 & 31;
        float4 v = ((const float4*)(Qg + (size_t)qrow*DM))[c];
        Qtf[(0*32+c)*130 + qrow] = v.x;
        Qtf[(1*32+c)*130 + qrow] = v.y;
        Qtf[(2*32+c)*130 + qrow] = v.z;
        Qtf[(3*32+c)*130 + qrow] = v.w;
    }

    const int g2 = t & 15, g1 = t >> 4;
    u64 acc[32];
#pragma unroll
    for (int i = 0; i < 32; ++i) acc[i] = 0;
    float m[8], z[8];
#pragma unroll
    for (int i = 0; i < 8; ++i){ m[i] = -1e30f; z[i] = 0.f; }

    for (int kt = 0; kt < 16; ++kt){
        __syncthreads();
        // Load K tile, duplicate each value into a u64 (k,k). Conflict-free stores.
#pragma unroll
        for (int mm = 0; mm < 16; ++mm){
            int f4 = mm*256 + t;
            int kl = f4 >> 5, c = f4 & 31;
            float4 v = ((const float4*)(Kg + (size_t)(kt*128 + kl)*DM))[c];
            u32 bx = __float_as_uint(v.x); Kd[kl*128 + 0*32 + c] = ((u64)bx<<32)|bx;
            u32 by = __float_as_uint(v.y); Kd[kl*128 + 1*32 + c] = ((u64)by<<32)|by;
            u32 bz = __float_as_uint(v.z); Kd[kl*128 + 2*32 + c] = ((u64)bz<<32)|bz;
            u32 bw = __float_as_uint(v.w); Kd[kl*128 + 3*32 + c] = ((u64)bw<<32)|bw;
        }
        __syncthreads();

        const u64* kr = Kd + (size_t)g1*8*128;
        const u64* qr = Qt + g2;
#pragma unroll 2
        for (int sd = 0; sd < 128; ++sd){
            u64 qq[4], kk[8];
#pragma unroll
            for (int p = 0; p < 4; ++p) qq[p] = qr[sd*65 + 16*p];
#pragma unroll
            for (int i = 0; i < 8; ++i) kk[i] = kr[i*128 + sd];
#pragma unroll
            for (int i = 0; i < 8; ++i)
#pragma unroll
                for (int p = 0; p < 4; ++p)
                    ffma2(acc[i*4+p], kk[i], qq[p]);
        }

        // Online softmax update per query (lo/hi halves of each pair).
#pragma unroll
        for (int p = 0; p < 4; ++p){
            float sl[8], sh[8];
#pragma unroll
            for (int i = 0; i < 8; ++i){
                u64 a = acc[i*4+p];
                sl[i] = __uint_as_float((u32)a);
                sh[i] = __uint_as_float((u32)(a >> 32));
                acc[i*4+p] = 0;
            }
            float mt = sl[0], mt2 = sh[0];
#pragma unroll
            for (int i = 1; i < 8; ++i){ mt = fmaxf(mt, sl[i]); mt2 = fmaxf(mt2, sh[i]); }
            {
                float mn = fmaxf(m[2*p], mt);
                float s = 0.f;
#pragma unroll
                for (int i = 0; i < 8; ++i) s += __expf(sl[i]-mn);
                z[2*p] = z[2*p]*__expf(m[2*p]-mn) + s;
                m[2*p] = mn;
            }
            {
                float mn = fmaxf(m[2*p+1], mt2);
                float s = 0.f;
#pragma unroll
                for (int i = 0; i < 8; ++i) s += __expf(sh[i]-mn);
                z[2*p+1] = z[2*p+1]*__expf(m[2*p+1]-mn) + s;
                m[2*p+1] = mn;
            }
        }
    }

    // Reduce over key-groups g1: first pair g1^1 via shfl(16), then 8 warps via smem.
    const int lane = t & 31, wid = t >> 5;
#pragma unroll
    for (int jj = 0; jj < 8; ++jj){
        float mo = __shfl_xor_sync(0xffffffffu, m[jj], 16);
        float zo = __shfl_xor_sync(0xffffffffu, z[jj], 16);
        float mn = fmaxf(m[jj], mo);
        z[jj] = z[jj]*__expf(m[jj]-mn) + zo*__expf(mo-mn);
        m[jj] = mn;
    }
    if (lane < 16){
#pragma unroll
        for (int p = 0; p < 4; ++p){
            mz[wid*128 + 2*(16*p + g2) + 0] = make_float2(m[2*p],   z[2*p]);
            mz[wid*128 + 2*(16*p + g2) + 1] = make_float2(m[2*p+1], z[2*p+1]);
        }
    }
    __syncthreads();
    if (t < 128){
        float2 a = mz[t];
        float M = a.x, Zz = a.y;
#pragma unroll
        for (int w = 1; w < 8; ++w){
            float2 bb = mz[w*128 + t];
            float mn = fmaxf(M, bb.x);
            Zz = Zz*__expf(M-mn) + bb.y*__expf(bb.x-mn);
            M = mn;
        }
        int rowbase = hb*SEQ + qt*128;
        g_m[rowbase + t] = M;
        g_z[rowbase + t] = Zz;
    }
}

// ---------------------------------------------------------------------------
// Kernel 3: per (b,s) block: each warp = one head. Recompute the 32 selected
// scores (coalesced K gather + warp reduction), renormalized weights
// w_i = e_i / (sumE + 1e-5*Z)  [exact rewrite of (e_i/Z)/(sumE/Z + 1e-5)],
// weighted V gather, then fused LayerNorm over the 1024-dim concatenated row.
// ---------------------------------------------------------------------------
__global__ __launch_bounds__(256) void out_kernel(
    const float* __restrict__ q, const float* __restrict__ k, const float* __restrict__ v,
    const float* __restrict__ gamma, const float* __restrict__ beta, float* __restrict__ out)
{
    const int bs = blockIdx.x;
    const int b = bs >> 11, s = bs & (SEQ-1);
    const int t = threadIdx.x, h = t >> 5, lane = t & 31;
    const int row = (b*NH + h)*SEQ + s;
    __shared__ float se[8][32];
    __shared__ int   sk[8][32];
    __shared__ float sout[1024];
    __shared__ float sred[8][2];

    const float* qp = q + (size_t)(b*SEQ + s)*DM + h*HD;
    float4 q4 = ((const float4*)qp)[lane];
    const float mrow = g_m[row];
    const float Zrow = g_z[row];
    sk[h][lane] = g_topk[(size_t)row*TOPK + lane];
    __syncwarp();
    const float* kb = k + (size_t)b*SEQ*DM + h*HD;
    const float* vb = v + (size_t)b*SEQ*DM + h*HD;

    float sumE = 0.f;
#pragma unroll 4
    for (int j = 0; j < 32; ++j){
        int kj = sk[h][j];
        float4 k4 = ((const float4*)(kb + (size_t)kj*DM))[lane];
        float p = q4.x*k4.x + q4.y*k4.y + q4.z*k4.z + q4.w*k4.w;
#pragma unroll
        for (int o = 16; o; o >>= 1) p += __shfl_xor_sync(0xffffffffu, p, o);
        float e = __expf(p - mrow);
        sumE += e;
        if (lane == 0) se[h][j] = e;
    }
    __syncwarp();
    float rden = 1.f / (sumE + 1e-5f*Zrow);

    float4 acc = make_float4(0.f,0.f,0.f,0.f);
#pragma unroll 4
    for (int j = 0; j < 32; ++j){
        float w = se[h][j] * rden;
        int kj = sk[h][j];
        float4 v4 = ((const float4*)(vb + (size_t)kj*DM))[lane];
        acc.x += w*v4.x; acc.y += w*v4.y; acc.z += w*v4.z; acc.w += w*v4.w;
    }
    ((float4*)sout)[h*32 + lane] = acc;
    __syncthreads();

    float4 x = ((const float4*)sout)[t];
    float ps = x.x + x.y + x.z + x.w;
    float pq = x.x*x.x + x.y*x.y + x.z*x.z + x.w*x.w;
#pragma unroll
    for (int o = 16; o; o >>= 1){
        ps += __shfl_xor_sync(0xffffffffu, ps, o);
        pq += __shfl_xor_sync(0xffffffffu, pq, o);
    }
    if (lane == 0){ sred[h][0] = ps; sred[h][1] = pq; }
    __syncthreads();
    float Sm = 0.f, Sq = 0.f;
#pragma unroll
    for (int w = 0; w < 8; ++w){ Sm += sred[w][0]; Sq += sred[w][1]; }
    float mu  = Sm * (1.f/1024.f);
    float var = Sq * (1.f/1024.f) - mu*mu;
    float r   = rsqrtf(var + 1e-5f);
    float4 g4 = ((const float4*)gamma)[t];
    float4 b4 = ((const float4*)beta)[t];
    float4 y;
    y.x = (x.x-mu)*r*g4.x + b4.x;
    y.y = (x.y-mu)*r*g4.y + b4.y;
    y.z = (x.z-mu)*r*g4.z + b4.z;
    y.w = (x.w-mu)*r*g4.w + b4.w;
    ((float4*)(out + (size_t)bs*DM))[t] = y;
}

// ---------------------------------------------------------------------------
extern "C" void kernel_launch(void* const* d_in, const int* in_sizes, int n_in,
                              void* d_out, int out_size){
    const float* q     = (const float*)d_in[0];
    const float* k     = (const float*)d_in[1];
    const float* v     = (const float*)d_in[2];
    const float* aw    = (const float*)d_in[3];
    const float* gamma = (const float*)d_in[4];
    const float* beta  = (const float*)d_in[5];
    float* out = (float*)d_out;

    cudaFuncSetAttribute(mz_kernel, cudaFuncAttributeMaxDynamicSharedMemorySize, SMEM2_BYTES);

    topk_kernel<<<NROWS, 256>>>(aw);
    mz_kernel<<<NB*NH*16, 256, SMEM2_BYTES>>>(q, k);
    out_kernel<<<NB*SEQ, 256>>>(q, k, v, gamma, beta, out);
}

// round 7
// speedup vs baseline: 2.9302x; 2.9302x over previous
#include <cuda_runtime.h>

typedef unsigned long long u64;
typedef unsigned int u32;

#define SEQ   2048
#define DM    1024
#define NH    8
#define HD    128
#define NB    2
#define NROWS (NB*NH*SEQ)
#define TOPK  32

__device__ int   g_topk[NROWS*TOPK];
__device__ float g_m[NROWS];
__device__ float g_z[NROWS];

__device__ __forceinline__ u32 fkey(float f){
    u32 b = __float_as_uint(f);
    return (b & 0x80000000u) ? ~b : (b | 0x80000000u);
}

// ---------------------------------------------------------------------------
// Kernel 1 v2: warp-per-row exact top-32 (value desc, index asc).
// Threshold pre-filter (>=1.9 => E[~59] candidates) via ballot compaction,
// then 32 warp-argmax rounds over <=128 candidates (4 u64 regs/lane).
// Exact global-rescan fallback (strict-descending threshold) if the filter
// yields <32 or >128 candidates (~1e-4 of rows / never, respectively).
// ---------------------------------------------------------------------------
#define TH0 1.9f
#define CANDMAX 128

__global__ __launch_bounds__(256) void topk_kernel(const float* __restrict__ aw){
    __shared__ u64 cand[8][CANDMAX];
    const int wid = threadIdx.x >> 5, lane = threadIdx.x & 31;
    const int row = blockIdx.x*8 + wid;
    const float* __restrict__ ar = aw + (size_t)row * SEQ;

    u32 nc = 0;
#pragma unroll
    for (int it = 0; it < 16; ++it){
        float4 v = ((const float4*)ar)[it*32 + lane];
        float vs[4] = {v.x, v.y, v.z, v.w};
#pragma unroll
        for (int j = 0; j < 4; ++j){
            bool pred = vs[j] >= TH0;
            u32 msk = __ballot_sync(0xffffffffu, pred);
            if (pred){
                u32 pos = nc + __popc(msk & ((1u << lane) - 1u));
                int idx = (it*32 + lane)*4 + j;
                if (pos < CANDMAX)
                    cand[wid][pos] = ((u64)fkey(vs[j]) << 32) | (u32)(SEQ-1-idx);
            }
            nc += __popc(msk);
        }
    }
    __syncwarp();
    int* outp = g_topk + (size_t)row * TOPK;

    if (nc >= TOPK && nc <= CANDMAX){
        u64 kv[4];
#pragma unroll
        for (int j = 0; j < 4; ++j){
            u32 p = lane + j*32;
            kv[j] = (p < nc) ? cand[wid][p] : 0ull;
        }
        for (int r = 0; r < TOPK; ++r){
            u64 loc = kv[0];
#pragma unroll
            for (int j = 1; j < 4; ++j) loc = kv[j] > loc ? kv[j] : loc;
#pragma unroll
            for (int o = 16; o; o >>= 1){
                u64 w = __shfl_xor_sync(0xffffffffu, loc, o);
                loc = w > loc ? w : loc;
            }
            if (lane == 0) outp[r] = (SEQ-1) - (int)(u32)loc;
#pragma unroll
            for (int j = 0; j < 4; ++j) if (kv[j] == loc) kv[j] = 0ull;
        }
    } else {
        // exact fallback: strict-descending selection over the full row
        u64 W = ~0ull;
        for (int r = 0; r < TOPK; ++r){
            u64 loc = 0;
            for (int j = 0; j < 64; ++j){
                int idx = lane + j*32;
                u64 key = ((u64)fkey(ar[idx]) << 32) | (u32)(SEQ-1-idx);
                if (key < W && key > loc) loc = key;
            }
#pragma unroll
            for (int o = 16; o; o >>= 1){
                u64 w = __shfl_xor_sync(0xffffffffu, loc, o);
                loc = w > loc ? w : loc;
            }
            if (lane == 0) outp[r] = (SEQ-1) - (int)(u32)loc;
            W = loc;
        }
    }
}

// ---------------------------------------------------------------------------
// Kernel 2 v2: per-row (m, Z) via dense-pair FFMA2 (2.0 B smem / FFMA2).
// Both K and Q tiles stored transposed [sd][64 u64 pairs], XOR-swizzled
// (col' = pair ^ ((sd>>2)&15), row stride 128 floats): inner-loop reads are
// bank-conflict-free; transpose stores are 2-way.
// Thread (g1=t>>4, g2=t&15): key pairs {i*16+g1}, query pairs {p*16+g2}.
// accA[i][p] += (k0,k1)*(q0,q1);  accB[i][p] += (k0,k1)*(q1,q0).
// ---------------------------------------------------------------------------
__device__ __forceinline__ void ffma2(u64 &d, u64 a, u64 b){
    asm("fma.rn.f32x2 %0, %1, %2, %0;" : "+l"(d) : "l"(a), "l"(b));
}
__device__ __forceinline__ u64 swap_u64(u64 x){
    u32 lo = (u32)x, hi = (u32)(x >> 32);
    return ((u64)lo << 32) | (u64)hi;
}

#define SMEM2_BYTES ((8192 + 8192 + 1024)*8)

__global__ __launch_bounds__(256,1) void mz_kernel(const float* __restrict__ q,
                                                   const float* __restrict__ k){
    extern __shared__ u64 sm[];
    u64*    Qt  = sm;                  float* Qtf = (float*)Qt;
    u64*    Kt  = sm + 8192;           float* Ktf = (float*)Kt;
    float2* mzs = (float2*)(sm + 16384);

    const int t  = threadIdx.x;
    const int hb = blockIdx.x >> 4;
    const int qt = blockIdx.x & 15;
    const int b  = hb >> 3, h = hb & 7;
    const float* Qg = q + ((size_t)(b*SEQ + qt*128))*DM + h*HD;
    const float* Kg = k + (size_t)b*SEQ*DM + h*HD;
    const int g2 = t & 15, g1 = t >> 4;

    // Q tile: load + swizzled transpose (once)
#pragma unroll
    for (int mm = 0; mm < 16; ++mm){
        int f4 = mm*256 + t;
        int qr = f4 >> 5, c = f4 & 31;
        float4 v = ((const float4*)(Qg + (size_t)qr*DM))[c];
        int bc = ((qr >> 1) ^ (c & 15))*2 + (qr & 1);
        Qtf[(4*c+0)*128 + bc] = v.x;
        Qtf[(4*c+1)*128 + bc] = v.y;
        Qtf[(4*c+2)*128 + bc] = v.z;
        Qtf[(4*c+3)*128 + bc] = v.w;
    }

    u64 accA[16], accB[16];
#pragma unroll
    for (int i = 0; i < 16; ++i){ accA[i] = 0; accB[i] = 0; }
    float m[8], z[8];
#pragma unroll
    for (int i = 0; i < 8; ++i){ m[i] = -1e30f; z[i] = 0.f; }

    for (int kt = 0; kt < 16; ++kt){
        __syncthreads();
#pragma unroll
        for (int mm = 0; mm < 16; ++mm){
            int f4 = mm*256 + t;
            int kr = f4 >> 5, c = f4 & 31;
            float4 v = ((const float4*)(Kg + (size_t)(kt*128 + kr)*DM))[c];
            int bc = ((kr >> 1) ^ (c & 15))*2 + (kr & 1);
            Ktf[(4*c+0)*128 + bc] = v.x;
            Ktf[(4*c+1)*128 + bc] = v.y;
            Ktf[(4*c+2)*128 + bc] = v.z;
            Ktf[(4*c+3)*128 + bc] = v.w;
        }
        __syncthreads();

        for (int q4 = 0; q4 < 32; ++q4){       // sd = q4*4 + u
            const int C = q4 & 15;
            const u64* kb = Kt + (size_t)q4*256;
            const u64* qb = Qt + (size_t)q4*256;
            u32 kc[4], qc[4];
#pragma unroll
            for (int i = 0; i < 4; ++i) kc[i] = (u32)((i*16 + g1) ^ C);
#pragma unroll
            for (int p = 0; p < 4; ++p) qc[p] = (u32)((p*16 + g2) ^ C);
#pragma unroll
            for (int u = 0; u < 4; ++u){
                u64 kk[4], qq[4];
#pragma unroll
                for (int i = 0; i < 4; ++i) kk[i] = kb[u*64 + kc[i]];
#pragma unroll
                for (int p = 0; p < 4; ++p) qq[p] = qb[u*64 + qc[p]];
#pragma unroll
                for (int p = 0; p < 4; ++p){
                    u64 qs = swap_u64(qq[p]);
#pragma unroll
                    for (int i = 0; i < 4; ++i){
                        ffma2(accA[i*4+p], kk[i], qq[p]);
                        ffma2(accB[i*4+p], kk[i], qs);
                    }
                }
            }
        }

        // per-tile online softmax update (8 queries x 8 keys per thread)
#pragma unroll
        for (int p = 0; p < 4; ++p){
            float s0[8], s1[8];
#pragma unroll
            for (int i = 0; i < 4; ++i){
                u64 a = accA[i*4+p], bb = accB[i*4+p];
                s0[2*i]   = __uint_as_float((u32)a);          // k even, q even
                s0[2*i+1] = __uint_as_float((u32)(bb >> 32)); // k odd,  q even
                s1[2*i]   = __uint_as_float((u32)bb);         // k even, q odd
                s1[2*i+1] = __uint_as_float((u32)(a >> 32));  // k odd,  q odd
                accA[i*4+p] = 0; accB[i*4+p] = 0;
            }
            {
                float mt = s0[0];
#pragma unroll
                for (int i = 1; i < 8; ++i) mt = fmaxf(mt, s0[i]);
                float mn = fmaxf(m[2*p], mt);
                float s = 0.f;
#pragma unroll
                for (int i = 0; i < 8; ++i) s += __expf(s0[i] - mn);
                z[2*p] = z[2*p]*__expf(m[2*p] - mn) + s;
                m[2*p] = mn;
            }
            {
                float mt = s1[0];
#pragma unroll
                for (int i = 1; i < 8; ++i) mt = fmaxf(mt, s1[i]);
                float mn = fmaxf(m[2*p+1], mt);
                float s = 0.f;
#pragma unroll
                for (int i = 0; i < 8; ++i) s += __expf(s1[i] - mn);
                z[2*p+1] = z[2*p+1]*__expf(m[2*p+1] - mn) + s;
                m[2*p+1] = mn;
            }
        }
    }

    // reduce over key-groups: g1 pair via shfl(16), then 8 warps via smem
    const int lane = t & 31, wid = t >> 5;
#pragma unroll
    for (int jj = 0; jj < 8; ++jj){
        float mo = __shfl_xor_sync(0xffffffffu, m[jj], 16);
        float zo = __shfl_xor_sync(0xffffffffu, z[jj], 16);
        float mn = fmaxf(m[jj], mo);
        z[jj] = z[jj]*__expf(m[jj]-mn) + zo*__expf(mo-mn);
        m[jj] = mn;
    }
    if (lane < 16){
#pragma unroll
        for (int p = 0; p < 4; ++p){
            int qp = p*16 + g2;
            mzs[wid*128 + 2*qp + 0] = make_float2(m[2*p],   z[2*p]);
            mzs[wid*128 + 2*qp + 1] = make_float2(m[2*p+1], z[2*p+1]);
        }
    }
    __syncthreads();
    if (t < 128){
        float2 a = mzs[t];
        float M = a.x, Zz = a.y;
#pragma unroll
        for (int w = 1; w < 8; ++w){
            float2 bb = mzs[w*128 + t];
            float mn = fmaxf(M, bb.x);
            Zz = Zz*__expf(M-mn) + bb.y*__expf(bb.x-mn);
            M = mn;
        }
        int rowbase = hb*SEQ + qt*128;
        g_m[rowbase + t] = M;
        g_z[rowbase + t] = Zz;
    }
}

// ---------------------------------------------------------------------------
// Kernel 3: recompute 32 selected scores, renormalize, V gather, fused LN.
// ---------------------------------------------------------------------------
__global__ __launch_bounds__(256) void out_kernel(
    const float* __restrict__ q, const float* __restrict__ k, const float* __restrict__ v,
    const float* __restrict__ gamma, const float* __restrict__ beta, float* __restrict__ out)
{
    const int bs = blockIdx.x;
    const int b = bs >> 11, s = bs & (SEQ-1);
    const int t = threadIdx.x, h = t >> 5, lane = t & 31;
    const int row = (b*NH + h)*SEQ + s;
    __shared__ float se[8][32];
    __shared__ int   sk[8][32];
    __shared__ float sout[1024];
    __shared__ float sred[8][2];

    const float* qp = q + (size_t)(b*SEQ + s)*DM + h*HD;
    float4 q4 = ((const float4*)qp)[lane];
    const float mrow = g_m[row];
    const float Zrow = g_z[row];
    sk[h][lane] = g_topk[(size_t)row*TOPK + lane];
    __syncwarp();
    const float* kb = k + (size_t)b*SEQ*DM + h*HD;
    const float* vb = v + (size_t)b*SEQ*DM + h*HD;

    float sumE = 0.f;
#pragma unroll 4
    for (int j = 0; j < 32; ++j){
        int kj = sk[h][j];
        float4 k4 = ((const float4*)(kb + (size_t)kj*DM))[lane];
        float p = q4.x*k4.x + q4.y*k4.y + q4.z*k4.z + q4.w*k4.w;
#pragma unroll
        for (int o = 16; o; o >>= 1) p += __shfl_xor_sync(0xffffffffu, p, o);
        float e = __expf(p - mrow);
        sumE += e;
        if (lane == 0) se[h][j] = e;
    }
    __syncwarp();
    float rden = 1.f / (sumE + 1e-5f*Zrow);

    float4 acc = make_float4(0.f,0.f,0.f,0.f);
#pragma unroll 4
    for (int j = 0; j < 32; ++j){
        float w = se[h][j] * rden;
        int kj = sk[h][j];
        float4 v4 = ((const float4*)(vb + (size_t)kj*DM))[lane];
        acc.x += w*v4.x; acc.y += w*v4.y; acc.z += w*v4.z; acc.w += w*v4.w;
    }
    ((float4*)sout)[h*32 + lane] = acc;
    __syncthreads();

    float4 x = ((const float4*)sout)[t];
    float ps = x.x + x.y + x.z + x.w;
    float pq = x.x*x.x + x.y*x.y + x.z*x.z + x.w*x.w;
#pragma unroll
    for (int o = 16; o; o >>= 1){
        ps += __shfl_xor_sync(0xffffffffu, ps, o);
        pq += __shfl_xor_sync(0xffffffffu, pq, o);
    }
    if (lane == 0){ sred[h][0] = ps; sred[h][1] = pq; }
    __syncthreads();
    float Sm = 0.f, Sq = 0.f;
#pragma unroll
    for (int w = 0; w < 8; ++w){ Sm += sred[w][0]; Sq += sred[w][1]; }
    float mu  = Sm * (1.f/1024.f);
    float var = Sq * (1.f/1024.f) - mu*mu;
    float r   = rsqrtf(var + 1e-5f);
    float4 g4 = ((const float4*)gamma)[t];
    float4 b4 = ((const float4*)beta)[t];
    float4 y;
    y.x = (x.x-mu)*r*g4.x + b4.x;
    y.y = (x.y-mu)*r*g4.y + b4.y;
    y.z = (x.z-mu)*r*g4.z + b4.z;
    y.w = (x.w-mu)*r*g4.w + b4.w;
    ((float4*)(out + (size_t)bs*DM))[t] = y;
}

// ---------------------------------------------------------------------------
extern "C" void kernel_launch(void* const* d_in, const int* in_sizes, int n_in,
                              void* d_out, int out_size){
    const float* q     = (const float*)d_in[0];
    const float* k     = (const float*)d_in[1];
    const float* v     = (const float*)d_in[2];
    const float* aw    = (const float*)d_in[3];
    const float* gamma = (const float*)d_in[4];
    const float* beta  = (const float*)d_in[5];
    float* out = (float*)d_out;

    cudaFuncSetAttribute(mz_kernel, cudaFuncAttributeMaxDynamicSharedMemorySize, SMEM2_BYTES);

    topk_kernel<<<NROWS/8, 256>>>(aw);
    mz_kernel<<<NB*NH*16, 256, SMEM2_BYTES>>>(q, k);
    out_kernel<<<NB*SEQ, 256>>>(q, k, v, gamma, beta, out);
}

// round 9
// speedup vs baseline: 3.1813x; 1.0857x over previous
#include <cuda_runtime.h>

typedef unsigned long long u64;
typedef unsigned int u32;

#define SEQ   2048
#define DM    1024
#define NH    8
#define HD    128
#define NB    2
#define NROWS (NB*NH*SEQ)
#define TOPK  32

__device__ int   g_topk[NROWS*TOPK];
__device__ float g_zpart[4][NROWS];

__device__ __forceinline__ u32 fkey(float f){
    u32 b = __float_as_uint(f);
    return (b & 0x80000000u) ? ~b : (b | 0x80000000u);
}

// ---------------------------------------------------------------------------
// Kernel 1: warp-per-row exact top-32 (value desc, index asc).
// Threshold pre-filter (>=1.9 => E[~59] candidates) via predicated smem-atomic
// compaction, then 32 warp-argmax rounds over <=128 candidates.
// Exact global-rescan fallback if the filter yields <32 or >128 candidates.
// ---------------------------------------------------------------------------
#define TH0 1.9f
#define CANDMAX 128

__global__ __launch_bounds__(256) void topk_kernel(const float* __restrict__ aw){
    __shared__ u64 cand[8][CANDMAX];
    __shared__ u32 cnt[8];
    const int wid = threadIdx.x >> 5, lane = threadIdx.x & 31;
    const int row = blockIdx.x*8 + wid;
    const float* __restrict__ ar = aw + (size_t)row * SEQ;
    if (lane == 0) cnt[wid] = 0;
    __syncwarp();
#pragma unroll
    for (int it = 0; it < 16; ++it){
        float4 v = ((const float4*)ar)[it*32 + lane];
        float vs[4] = {v.x, v.y, v.z, v.w};
#pragma unroll
        for (int j = 0; j < 4; ++j){
            if (vs[j] >= TH0){
                u32 pos = atomicAdd(&cnt[wid], 1u);
                int idx = (it*32 + lane)*4 + j;
                if (pos < CANDMAX)
                    cand[wid][pos] = ((u64)fkey(vs[j]) << 32) | (u32)(SEQ-1-idx);
            }
        }
    }
    __syncwarp();
    u32 nc = cnt[wid];
    int* outp = g_topk + (size_t)row * TOPK;

    if (nc >= TOPK && nc <= CANDMAX){
        u64 kv[4];
#pragma unroll
        for (int j = 0; j < 4; ++j){
            u32 p = lane + j*32;
            kv[j] = (p < nc) ? cand[wid][p] : 0ull;
        }
        for (int r = 0; r < TOPK; ++r){
            u64 loc = kv[0];
#pragma unroll
            for (int j = 1; j < 4; ++j) loc = kv[j] > loc ? kv[j] : loc;
#pragma unroll
            for (int o = 16; o; o >>= 1){
                u64 w = __shfl_xor_sync(0xffffffffu, loc, o);
                loc = w > loc ? w : loc;
            }
            if (lane == 0) outp[r] = (SEQ-1) - (int)(u32)loc;
#pragma unroll
            for (int j = 0; j < 4; ++j) if (kv[j] == loc) kv[j] = 0ull;
        }
    } else {
        // exact fallback: strict-descending selection over the full row
        u64 W = ~0ull;
        for (int r = 0; r < TOPK; ++r){
            u64 loc = 0;
            for (int j = 0; j < 64; ++j){
                int idx = lane + j*32;
                u64 key = ((u64)fkey(ar[idx]) << 32) | (u32)(SEQ-1-idx);
                if (key < W && key > loc) loc = key;
            }
#pragma unroll
            for (int o = 16; o; o >>= 1){
                u64 w = __shfl_xor_sync(0xffffffffu, loc, o);
                loc = w > loc ? w : loc;
            }
            if (lane == 0) outp[r] = (SEQ-1) - (int)(u32)loc;
            W = loc;
        }
    }
}

// ---------------------------------------------------------------------------
// Kernel 2: partial Z per (hb, qtile, kquarter) via dense-pair FFMA2.
// Grid = 16hb x 16qt x 4kq = 1024 blocks (~7 balanced waves at 1 CTA/SM).
// No max-tracking: scores bounded (|s|<~75), Z = sum(exp(s)) directly.
// K/Q tiles transposed [sd][64 u64 pairs], XOR-swizzled, conflict-free.
// ---------------------------------------------------------------------------
__device__ __forceinline__ void ffma2(u64 &d, u64 a, u64 b){
    asm("fma.rn.f32x2 %0, %1, %2, %0;" : "+l"(d) : "l"(a), "l"(b));
}
__device__ __forceinline__ u64 swap_u64(u64 x){
    u32 lo = (u32)x, hi = (u32)(x >> 32);
    return ((u64)lo << 32) | (u64)hi;
}

#define SMEM2_BYTES ((8192 + 8192)*8 + 4096)

__global__ __launch_bounds__(256,1) void mz_kernel(const float* __restrict__ q,
                                                   const float* __restrict__ k){
    extern __shared__ u64 sm[];
    u64*   Qt  = sm;            float* Qtf = (float*)Qt;
    u64*   Kt  = sm + 8192;     float* Ktf = (float*)Kt;
    float* zs  = (float*)(sm + 16384);   // [8 warps][128 queries]

    const int t  = threadIdx.x;
    const int hb = blockIdx.x >> 6;
    const int qt = (blockIdx.x >> 2) & 15;
    const int kq = blockIdx.x & 3;
    const int b  = hb >> 3, h = hb & 7;
    const float* Qg = q + ((size_t)(b*SEQ + qt*128))*DM + h*HD;
    const float* Kg = k + (size_t)b*SEQ*DM + h*HD;
    const int g2 = t & 15, g1 = t >> 4;

    // Q tile: load + swizzled transpose (once)
#pragma unroll
    for (int mm = 0; mm < 16; ++mm){
        int f4 = mm*256 + t;
        int qr = f4 >> 5, c = f4 & 31;
        float4 v = ((const float4*)(Qg + (size_t)qr*DM))[c];
        int bc = ((qr >> 1) ^ (c & 15))*2 + (qr & 1);
        Qtf[(4*c+0)*128 + bc] = v.x;
        Qtf[(4*c+1)*128 + bc] = v.y;
        Qtf[(4*c+2)*128 + bc] = v.z;
        Qtf[(4*c+3)*128 + bc] = v.w;
    }

    u64 accA[16], accB[16];
#pragma unroll
    for (int i = 0; i < 16; ++i){ accA[i] = 0; accB[i] = 0; }
    float z[8];
#pragma unroll
    for (int i = 0; i < 8; ++i) z[i] = 0.f;

    for (int kt2 = 0; kt2 < 4; ++kt2){
        const int kt = kq*4 + kt2;
        __syncthreads();
#pragma unroll
        for (int mm = 0; mm < 16; ++mm){
            int f4 = mm*256 + t;
            int kr = f4 >> 5, c = f4 & 31;
            float4 v = ((const float4*)(Kg + (size_t)(kt*128 + kr)*DM))[c];
            int bc = ((kr >> 1) ^ (c & 15))*2 + (kr & 1);
            Ktf[(4*c+0)*128 + bc] = v.x;
            Ktf[(4*c+1)*128 + bc] = v.y;
            Ktf[(4*c+2)*128 + bc] = v.z;
            Ktf[(4*c+3)*128 + bc] = v.w;
        }
        __syncthreads();

        for (int q4 = 0; q4 < 32; ++q4){       // sd = q4*4 + u
            const int C = q4 & 15;
            const u64* kb = Kt + (size_t)q4*256;
            const u64* qb = Qt + (size_t)q4*256;
            u32 kc[4], qc[4];
#pragma unroll
            for (int i = 0; i < 4; ++i) kc[i] = (u32)((i*16 + g1) ^ C);
#pragma unroll
            for (int p = 0; p < 4; ++p) qc[p] = (u32)((p*16 + g2) ^ C);
#pragma unroll
            for (int u = 0; u < 4; ++u){
                u64 kk[4], qq[4];
#pragma unroll
                for (int i = 0; i < 4; ++i) kk[i] = kb[u*64 + kc[i]];
#pragma unroll
                for (int p = 0; p < 4; ++p) qq[p] = qb[u*64 + qc[p]];
#pragma unroll
                for (int p = 0; p < 4; ++p){
                    u64 qs = swap_u64(qq[p]);
#pragma unroll
                    for (int i = 0; i < 4; ++i){
                        ffma2(accA[i*4+p], kk[i], qq[p]);
                        ffma2(accB[i*4+p], kk[i], qs);
                    }
                }
            }
        }

        // epilogue: z += sum(exp(score)), no max needed
#pragma unroll
        for (int p = 0; p < 4; ++p){
            float s0 = 0.f, s1 = 0.f;
#pragma unroll
            for (int i = 0; i < 4; ++i){
                u64 a = accA[i*4+p], bb = accB[i*4+p];
                s0 += __expf(__uint_as_float((u32)a));          // k even, q even
                s0 += __expf(__uint_as_float((u32)(bb >> 32))); // k odd,  q even
                s1 += __expf(__uint_as_float((u32)bb));         // k even, q odd
                s1 += __expf(__uint_as_float((u32)(a >> 32)));  // k odd,  q odd
                accA[i*4+p] = 0; accB[i*4+p] = 0;
            }
            z[2*p]   += s0;
            z[2*p+1] += s1;
        }
    }

    // reduce over key-groups: g1 pair via shfl(16), then 8 warps via smem
    const int lane = t & 31, wid = t >> 5;
#pragma unroll
    for (int jj = 0; jj < 8; ++jj)
        z[jj] += __shfl_xor_sync(0xffffffffu, z[jj], 16);
    if (lane < 16){
#pragma unroll
        for (int p = 0; p < 4; ++p){
            int qp = p*16 + g2;
            zs[wid*128 + 2*qp + 0] = z[2*p];
            zs[wid*128 + 2*qp + 1] = z[2*p+1];
        }
    }
    __syncthreads();
    if (t < 128){
        float Zz = zs[t];
#pragma unroll
        for (int w = 1; w < 8; ++w) Zz += zs[w*128 + t];
        g_zpart[kq][hb*SEQ + qt*128 + t] = Zz;
    }
}

// ---------------------------------------------------------------------------
// Kernel 3: recompute 32 selected scores, renormalize with
// w_i = e^{s_i} / (sumE + 1e-5*Z), V gather, fused LayerNorm.
// ---------------------------------------------------------------------------
__global__ __launch_bounds__(256) void out_kernel(
    const float* __restrict__ q, const float* __restrict__ k, const float* __restrict__ v,
    const float* __restrict__ gamma, const float* __restrict__ beta, float* __restrict__ out)
{
    const int bs = blockIdx.x;
    const int b = bs >> 11, s = bs & (SEQ-1);
    const int t = threadIdx.x, h = t >> 5, lane = t & 31;
    const int row = (b*NH + h)*SEQ + s;
    __shared__ float se[8][32];
    __shared__ int   sk[8][32];
    __shared__ float sout[1024];
    __shared__ float sred[8][2];

    const float* qp = q + (size_t)(b*SEQ + s)*DM + h*HD;
    float4 q4 = ((const float4*)qp)[lane];
    const float Zrow = g_zpart[0][row] + g_zpart[1][row] + g_zpart[2][row] + g_zpart[3][row];
    sk[h][lane] = g_topk[(size_t)row*TOPK + lane];
    __syncwarp();
    const float* kb = k + (size_t)b*SEQ*DM + h*HD;
    const float* vb = v + (size_t)b*SEQ*DM + h*HD;

    float sumE = 0.f;
#pragma unroll 4
    for (int j = 0; j < 32; ++j){
        int kj = sk[h][j];
        float4 k4 = ((const float4*)(kb + (size_t)kj*DM))[lane];
        float p = q4.x*k4.x + q4.y*k4.y + q4.z*k4.z + q4.w*k4.w;
#pragma unroll
        for (int o = 16; o; o >>= 1) p += __shfl_xor_sync(0xffffffffu, p, o);
        float e = __expf(p);
        sumE += e;
        if (lane == 0) se[h][j] = e;
    }
    __syncwarp();
    float rden = 1.f / (sumE + 1e-5f*Zrow);

    float4 acc = make_float4(0.f,0.f,0.f,0.f);
#pragma unroll 4
    for (int j = 0; j < 32; ++j){
        float w = se[h][j] * rden;
        int kj = sk[h][j];
        float4 v4 = ((const float4*)(vb + (size_t)kj*DM))[lane];
        acc.x += w*v4.x; acc.y += w*v4.y; acc.z += w*v4.z; acc.w += w*v4.w;
    }
    ((float4*)sout)[h*32 + lane] = acc;
    __syncthreads();

    float4 x = ((const float4*)sout)[t];
    float ps = x.x + x.y + x.z + x.w;
    float pq = x.x*x.x + x.y*x.y + x.z*x.z + x.w*x.w;
#pragma unroll
    for (int o = 16; o; o >>= 1){
        ps += __shfl_xor_sync(0xffffffffu, ps, o);
        pq += __shfl_xor_sync(0xffffffffu, pq, o);
    }
    if (lane == 0){ sred[h][0] = ps; sred[h][1] = pq; }
    __syncthreads();
    float Sm = 0.f, Sq = 0.f;
#pragma unroll
    for (int w = 0; w < 8; ++w){ Sm += sred[w][0]; Sq += sred[w][1]; }
    float mu  = Sm * (1.f/1024.f);
    float var = Sq * (1.f/1024.f) - mu*mu;
    float r   = rsqrtf(var + 1e-5f);
    float4 g4 = ((const float4*)gamma)[t];
    float4 b4 = ((const float4*)beta)[t];
    float4 y;
    y.x = (x.x-mu)*r*g4.x + b4.x;
    y.y = (x.y-mu)*r*g4.y + b4.y;
    y.z = (x.z-mu)*r*g4.z + b4.z;
    y.w = (x.w-mu)*r*g4.w + b4.w;
    ((float4*)(out + (size_t)bs*DM))[t] = y;
}

// ---------------------------------------------------------------------------
extern "C" void kernel_launch(void* const* d_in, const int* in_sizes, int n_in,
                              void* d_out, int out_size){
    const float* q     = (const float*)d_in[0];
    const float* k     = (const float*)d_in[1];
    const float* v     = (const float*)d_in[2];
    const float* aw    = (const float*)d_in[3];
    const float* gamma = (const float*)d_in[4];
    const float* beta  = (const float*)d_in[5];
    float* out = (float*)d_out;

    cudaFuncSetAttribute(mz_kernel, cudaFuncAttributeMaxDynamicSharedMemorySize, SMEM2_BYTES);

    topk_kernel<<<NROWS/8, 256>>>(aw);
    mz_kernel<<<16*16*4, 256, SMEM2_BYTES>>>(q, k);
    out_kernel<<<NB*SEQ, 256>>>(q, k, v, gamma, beta, out);
}

// round 10
// speedup vs baseline: 3.3189x; 1.0433x over previous
#include <cuda_runtime.h>

typedef unsigned long long u64;
typedef unsigned int u32;

#define SEQ   2048
#define DM    1024
#define NH    8
#define HD    128
#define NB    2
#define NROWS (NB*NH*SEQ)
#define TOPK  32

__device__ int   g_topk[NROWS*TOPK];
__device__ float g_zpart[8][NROWS];

__device__ __forceinline__ u32 fkey(float f){
    u32 b = __float_as_uint(f);
    return (b & 0x80000000u) ? ~b : (b | 0x80000000u);
}

// ---------------------------------------------------------------------------
// Kernel 1: warp-per-row exact top-32 (value desc, index asc).
// max-of-8 prefilter branch (P(hit)~0.21) -> per-element checks only on hits.
// Then 32 warp-argmax rounds over <=128 candidates; exact fallback if the
// threshold filter yields <32 or >128 candidates.
// ---------------------------------------------------------------------------
#define TH0 1.9f
#define CANDMAX 128

__global__ __launch_bounds__(256) void topk_kernel(const float* __restrict__ aw){
    __shared__ u64 cand[8][CANDMAX];
    __shared__ u32 cnt[8];
    const int wid = threadIdx.x >> 5, lane = threadIdx.x & 31;
    const int row = blockIdx.x*8 + wid;
    const float* __restrict__ ar = aw + (size_t)row * SEQ;
    if (lane == 0) cnt[wid] = 0;
    __syncwarp();
#pragma unroll
    for (int it = 0; it < 8; ++it){
        float4 a = ((const float4*)ar)[it*64 + lane*2];
        float4 c4 = ((const float4*)ar)[it*64 + lane*2 + 1];
        float m8 = fmaxf(fmaxf(fmaxf(a.x,a.y), fmaxf(a.z,a.w)),
                         fmaxf(fmaxf(c4.x,c4.y), fmaxf(c4.z,c4.w)));
        if (m8 >= TH0){
            float vs[8] = {a.x,a.y,a.z,a.w,c4.x,c4.y,c4.z,c4.w};
            int base = it*256 + lane*8;
#pragma unroll
            for (int j = 0; j < 8; ++j){
                if (vs[j] >= TH0){
                    u32 pos = atomicAdd(&cnt[wid], 1u);
                    int idx = base + j;
                    if (pos < CANDMAX)
                        cand[wid][pos] = ((u64)fkey(vs[j]) << 32) | (u32)(SEQ-1-idx);
                }
            }
        }
    }
    __syncwarp();
    u32 nc = cnt[wid];
    int* outp = g_topk + (size_t)row * TOPK;

    if (nc >= TOPK && nc <= CANDMAX){
        u64 kv[4];
#pragma unroll
        for (int j = 0; j < 4; ++j){
            u32 p = lane + j*32;
            kv[j] = (p < nc) ? cand[wid][p] : 0ull;
        }
        for (int r = 0; r < TOPK; ++r){
            u64 loc = kv[0];
#pragma unroll
            for (int j = 1; j < 4; ++j) loc = kv[j] > loc ? kv[j] : loc;
#pragma unroll
            for (int o = 16; o; o >>= 1){
                u64 w = __shfl_xor_sync(0xffffffffu, loc, o);
                loc = w > loc ? w : loc;
            }
            if (lane == 0) outp[r] = (SEQ-1) - (int)(u32)loc;
#pragma unroll
            for (int j = 0; j < 4; ++j) if (kv[j] == loc) kv[j] = 0ull;
        }
    } else {
        // exact fallback: strict-descending selection over the full row
        u64 W = ~0ull;
        for (int r = 0; r < TOPK; ++r){
            u64 loc = 0;
            for (int j = 0; j < 64; ++j){
                int idx = lane + j*32;
                u64 key = ((u64)fkey(ar[idx]) << 32) | (u32)(SEQ-1-idx);
                if (key < W && key > loc) loc = key;
            }
#pragma unroll
            for (int o = 16; o; o >>= 1){
                u64 w = __shfl_xor_sync(0xffffffffu, loc, o);
                loc = w > loc ? w : loc;
            }
            if (lane == 0) outp[r] = (SEQ-1) - (int)(u32)loc;
            W = loc;
        }
    }
}

// ---------------------------------------------------------------------------
// Kernel 2: partial Z per (hb, 256-query tile, 256-key slice) via FFMA2.
// Grid = 16hb x 8qt x 8kq = 1024 blocks (~7 balanced waves, 1 CTA/SM).
// Thread tile: 16 keys (g1 = warp id -> all K smem reads are warp-uniform
// broadcasts, ~free on the crossbar) x 8 queries (g2 = lane -> conflict-free).
// Tiles stored transposed [sd][pairs] as u64, col-XOR-swizzled with c=sd>>2
// (store col = pair^c, read col = want^c -> retrieved pair = want, so the
// accumulator->key mapping is sd-invariant). No max-tracking (|s|<~75).
// ---------------------------------------------------------------------------
__device__ __forceinline__ void ffma2(u64 &d, u64 a, u64 b){
    asm("fma.rn.f32x2 %0, %1, %2, %0;" : "+l"(d) : "l"(a), "l"(b));
}
__device__ __forceinline__ u64 swap_u64(u64 x){
    u32 lo = (u32)x, hi = (u32)(x >> 32);
    return ((u64)lo << 32) | (u64)hi;
}

#define QT_U64 (128*128)        /* [sd][128 qpairs]  = 128 KB */
#define KT_U64 (128*64)         /* [sd][64  kpairs]  =  64 KB */
#define SMEM2_BYTES (QT_U64*8 + KT_U64*8 + 8*256*4)   /* 204800 B */

__global__ __launch_bounds__(256,1) void mz_kernel(const float* __restrict__ q,
                                                   const float* __restrict__ k){
    extern __shared__ u64 sm[];
    u64*   Qt  = sm;                 float* Qtf = (float*)Qt;
    u64*   Kt  = sm + QT_U64;        float* Ktf = (float*)Kt;
    float* zs  = (float*)(sm + QT_U64 + KT_U64);   // [8 warps][256 queries]

    const int t  = threadIdx.x;
    const int hb = blockIdx.x >> 6;
    const int qt = (blockIdx.x >> 3) & 7;
    const int kq = blockIdx.x & 7;
    const int b  = hb >> 3, h = hb & 7;
    const float* Qg = q + ((size_t)(b*SEQ + qt*256))*DM + h*HD;
    const float* Kg = k + ((size_t)(b*SEQ + kq*256))*DM + h*HD;
    const int g2 = t & 31, g1 = t >> 5;

    // Q tile: load + swizzled transpose (256 queries x 128 dims), once.
#pragma unroll
    for (int mm = 0; mm < 32; ++mm){
        int f4 = mm*256 + t;
        int qr = f4 >> 5, c = f4 & 31;
        float4 v = ((const float4*)(Qg + (size_t)qr*DM))[c];
        int col = ((qr >> 1) ^ c)*2 + (qr & 1);
        Qtf[(4*c+0)*256 + col] = v.x;
        Qtf[(4*c+1)*256 + col] = v.y;
        Qtf[(4*c+2)*256 + col] = v.z;
        Qtf[(4*c+3)*256 + col] = v.w;
    }

    u64 accA[32], accB[32];
#pragma unroll
    for (int i = 0; i < 32; ++i){ accA[i] = 0; accB[i] = 0; }
    float z[8];
#pragma unroll
    for (int i = 0; i < 8; ++i) z[i] = 0.f;

    for (int kt = 0; kt < 2; ++kt){
        __syncthreads();
        // K tile: 128 keys x 128 dims, swizzled transpose.
#pragma unroll
        for (int mm = 0; mm < 16; ++mm){
            int f4 = mm*256 + t;
            int kr = f4 >> 5, c = f4 & 31;
            float4 v = ((const float4*)(Kg + (size_t)(kt*128 + kr)*DM))[c];
            int col = ((kr >> 1) ^ c)*2 + (kr & 1);
            Ktf[(4*c+0)*128 + col] = v.x;
            Ktf[(4*c+1)*128 + col] = v.y;
            Ktf[(4*c+2)*128 + col] = v.z;
            Ktf[(4*c+3)*128 + col] = v.w;
        }
        __syncthreads();

#pragma unroll 1
        for (int q4 = 0; q4 < 32; ++q4){        // sd = q4*4 + u
            const u64* kb = Kt + (size_t)q4*256;
            const u64* qb = Qt + (size_t)q4*512;
            u32 kc[8], qc[4];
#pragma unroll
            for (int i = 0; i < 8; ++i) kc[i] = (u32)((i*8 + g1) ^ q4);
#pragma unroll
            for (int p = 0; p < 4; ++p) qc[p] = (u32)((p*32 + g2) ^ q4);
#pragma unroll
            for (int u = 0; u < 4; ++u){
                u64 kk[8], qq[4];
#pragma unroll
                for (int i = 0; i < 8; ++i) kk[i] = kb[u*64 + kc[i]];   // broadcast
#pragma unroll
                for (int p = 0; p < 4; ++p) qq[p] = qb[u*128 + qc[p]];
#pragma unroll
                for (int p = 0; p < 4; ++p){
                    u64 qs = swap_u64(qq[p]);
#pragma unroll
                    for (int i = 0; i < 8; ++i){
                        ffma2(accA[i*4+p], kk[i], qq[p]);
                        ffma2(accB[i*4+p], kk[i], qs);
                    }
                }
            }
        }

        // epilogue: z += sum(exp(score)); acc lo=(k_e*q_e), accB hi=(k_o*q_e), etc.
#pragma unroll
        for (int p = 0; p < 4; ++p){
            float s0 = 0.f, s1 = 0.f;
#pragma unroll
            for (int i = 0; i < 8; ++i){
                u64 a = accA[i*4+p], bb = accB[i*4+p];
                s0 += __expf(__uint_as_float((u32)a));
                s0 += __expf(__uint_as_float((u32)(bb >> 32)));
                s1 += __expf(__uint_as_float((u32)bb));
                s1 += __expf(__uint_as_float((u32)(a >> 32)));
                accA[i*4+p] = 0; accB[i*4+p] = 0;
            }
            z[2*p]   += s0;
            z[2*p+1] += s1;
        }
    }

    // cross-warp reduction over the 8 key-groups
    __syncthreads();
#pragma unroll
    for (int p = 0; p < 4; ++p){
        zs[g1*256 + 2*(p*32 + g2) + 0] = z[2*p];
        zs[g1*256 + 2*(p*32 + g2) + 1] = z[2*p+1];
    }
    __syncthreads();
    {
        float Zz = zs[t];
#pragma unroll
        for (int w = 1; w < 8; ++w) Zz += zs[w*256 + t];
        g_zpart[kq][hb*SEQ + qt*256 + t] = Zz;
    }
}

// ---------------------------------------------------------------------------
// Kernel 3: recompute 32 selected scores, renormalize with
// w_i = e^{s_i} / (sumE + 1e-5*Z), V gather, fused LayerNorm.
// ---------------------------------------------------------------------------
__global__ __launch_bounds__(256) void out_kernel(
    const float* __restrict__ q, const float* __restrict__ k, const float* __restrict__ v,
    const float* __restrict__ gamma, const float* __restrict__ beta, float* __restrict__ out)
{
    const int bs = blockIdx.x;
    const int b = bs >> 11, s = bs & (SEQ-1);
    const int t = threadIdx.x, h = t >> 5, lane = t & 31;
    const int row = (b*NH + h)*SEQ + s;
    __shared__ float se[8][32];
    __shared__ int   sk[8][32];
    __shared__ float sout[1024];
    __shared__ float sred[8][2];

    const float* qp = q + (size_t)(b*SEQ + s)*DM + h*HD;
    float4 q4 = ((const float4*)qp)[lane];
    float Zrow = 0.f;
#pragma unroll
    for (int j = 0; j < 8; ++j) Zrow += g_zpart[j][row];
    sk[h][lane] = g_topk[(size_t)row*TOPK + lane];
    __syncwarp();
    const float* kb = k + (size_t)b*SEQ*DM + h*HD;
    const float* vb = v + (size_t)b*SEQ*DM + h*HD;

    float sumE = 0.f;
#pragma unroll 4
    for (int j = 0; j < 32; ++j){
        int kj = sk[h][j];
        float4 k4 = ((const float4*)(kb + (size_t)kj*DM))[lane];
        float p = q4.x*k4.x + q4.y*k4.y + q4.z*k4.z + q4.w*k4.w;
#pragma unroll
        for (int o = 16; o; o >>= 1) p += __shfl_xor_sync(0xffffffffu, p, o);
        float e = __expf(p);
        sumE += e;
        if (lane == 0) se[h][j] = e;
    }
    __syncwarp();
    float rden = 1.f / (sumE + 1e-5f*Zrow);

    float4 acc = make_float4(0.f,0.f,0.f,0.f);
#pragma unroll 4
    for (int j = 0; j < 32; ++j){
        float w = se[h][j] * rden;
        int kj = sk[h][j];
        float4 v4 = ((const float4*)(vb + (size_t)kj*DM))[lane];
        acc.x += w*v4.x; acc.y += w*v4.y; acc.z += w*v4.z; acc.w += w*v4.w;
    }
    ((float4*)sout)[h*32 + lane] = acc;
    __syncthreads();

    float4 x = ((const float4*)sout)[t];
    float ps = x.x + x.y + x.z + x.w;
    float pq = x.x*x.x + x.y*x.y + x.z*x.z + x.w*x.w;
#pragma unroll
    for (int o = 16; o; o >>= 1){
        ps += __shfl_xor_sync(0xffffffffu, ps, o);
        pq += __shfl_xor_sync(0xffffffffu, pq, o);
    }
    if (lane == 0){ sred[h][0] = ps; sred[h][1] = pq; }
    __syncthreads();
    float Sm = 0.f, Sq = 0.f;
#pragma unroll
    for (int w = 0; w < 8; ++w){ Sm += sred[w][0]; Sq += sred[w][1]; }
    float mu  = Sm * (1.f/1024.f);
    float var = Sq * (1.f/1024.f) - mu*mu;
    float r   = rsqrtf(var + 1e-5f);
    float4 g4 = ((const float4*)gamma)[t];
    float4 b4 = ((const float4*)beta)[t];
    float4 y;
    y.x = (x.x-mu)*r*g4.x + b4.x;
    y.y = (x.y-mu)*r*g4.y + b4.y;
    y.z = (x.z-mu)*r*g4.z + b4.z;
    y.w = (x.w-mu)*r*g4.w + b4.w;
    ((float4*)(out + (size_t)bs*DM))[t] = y;
}

// ---------------------------------------------------------------------------
extern "C" void kernel_launch(void* const* d_in, const int* in_sizes, int n_in,
                              void* d_out, int out_size){
    const float* q     = (const float*)d_in[0];
    const float* k     = (const float*)d_in[1];
    const float* v     = (const float*)d_in[2];
    const float* aw    = (const float*)d_in[3];
    const float* gamma = (const float*)d_in[4];
    const float* beta  = (const float*)d_in[5];
    float* out = (float*)d_out;

    cudaFuncSetAttribute(mz_kernel, cudaFuncAttributeMaxDynamicSharedMemorySize, SMEM2_BYTES);

    topk_kernel<<<NROWS/8, 256>>>(aw);
    mz_kernel<<<16*8*8, 256, SMEM2_BYTES>>>(q, k);
    out_kernel<<<NB*SEQ, 256>>>(q, k, v, gamma, beta, out);
}

// round 11
// speedup vs baseline: 3.4802x; 1.0486x over previous
#include <cuda_runtime.h>

typedef unsigned long long u64;
typedef unsigned int u32;

#define SEQ   2048
#define DM    1024
#define NH    8
#define HD    128
#define NB    2
#define NROWS (NB*NH*SEQ)
#define TOPK  32

__device__ int   g_topk[NROWS*TOPK];
__device__ float g_zpart[8][NROWS];

__device__ __forceinline__ u32 fkey(float f){
    u32 b = __float_as_uint(f);
    return (b & 0x80000000u) ? ~b : (b | 0x80000000u);
}

// ---------------------------------------------------------------------------
// Kernel 1: warp-per-row exact top-32 (value desc, index asc).
// Scan: threshold prefilter (>=1.9, E[~59] cands) w/ predicated smem atomics.
// Selection: 32 rounds of REDUX.UMAX over split keys (value u32, inv-idx u32):
//   wmax = warp-max of values; widx = warp-max of inv_idx among holders of
//   wmax (= smallest original index); clear exactly that entry. Exact
//   stable-argsort tie-break; duplicates pop one per round.
// Exact full-row fallback if filter yields <32 or >128 candidates.
// ---------------------------------------------------------------------------
#define TH0 1.9f
#define CANDMAX 128

__global__ __launch_bounds__(256) void topk_kernel(const float* __restrict__ aw){
    __shared__ u64 cand[8][CANDMAX];
    __shared__ u32 cnt[8];
    const int wid = threadIdx.x >> 5, lane = threadIdx.x & 31;
    const int row = blockIdx.x*8 + wid;
    const float* __restrict__ ar = aw + (size_t)row * SEQ;
    if (lane == 0) cnt[wid] = 0;
    __syncwarp();
#pragma unroll
    for (int it = 0; it < 16; ++it){
        float4 v = ((const float4*)ar)[it*32 + lane];
        float vs[4] = {v.x, v.y, v.z, v.w};
#pragma unroll
        for (int j = 0; j < 4; ++j){
            if (vs[j] >= TH0){
                u32 pos = atomicAdd(&cnt[wid], 1u);
                int idx = (it*32 + lane)*4 + j;
                if (pos < CANDMAX)
                    cand[wid][pos] = ((u64)fkey(vs[j]) << 32) | (u32)(SEQ-1-idx);
            }
        }
    }
    __syncwarp();
    u32 nc = cnt[wid];
    int* outp = g_topk + (size_t)row * TOPK;

    if (nc >= TOPK && nc <= CANDMAX){
        u32 khi[4], klo[4];
#pragma unroll
        for (int j = 0; j < 4; ++j){
            u32 p = lane + j*32;
            u64 c = (p < nc) ? cand[wid][p] : 0ull;
            khi[j] = (u32)(c >> 32);
            klo[j] = (u32)c;
        }
        for (int r = 0; r < TOPK; ++r){
            u32 loc = max(max(khi[0], khi[1]), max(khi[2], khi[3]));
            u32 wmax = __reduce_max_sync(0xffffffffu, loc);
            u32 ci = 0;
#pragma unroll
            for (int j = 0; j < 4; ++j) if (khi[j] == wmax) ci = max(ci, klo[j]);
            u32 wi = __reduce_max_sync(0xffffffffu, ci);
            if (lane == 0) outp[r] = (SEQ-1) - (int)wi;
#pragma unroll
            for (int j = 0; j < 4; ++j)
                if (khi[j] == wmax && klo[j] == wi) khi[j] = 0u;
        }
    } else {
        // exact fallback: strict-descending selection over the full row
        u64 W = ~0ull;
        for (int r = 0; r < TOPK; ++r){
            u64 loc = 0;
            for (int j = 0; j < 64; ++j){
                int idx = lane + j*32;
                u64 key = ((u64)fkey(ar[idx]) << 32) | (u32)(SEQ-1-idx);
                if (key < W && key > loc) loc = key;
            }
#pragma unroll
            for (int o = 16; o; o >>= 1){
                u64 w = __shfl_xor_sync(0xffffffffu, loc, o);
                loc = w > loc ? w : loc;
            }
            if (lane == 0) outp[r] = (SEQ-1) - (int)(u32)loc;
            W = loc;
        }
    }
}

// ---------------------------------------------------------------------------
// Kernel 2: partial Z per (hb, 256-query tile, 256-key slice) via FFMA2.
// 512 threads (16 warps -> 4/SMSP for latency hiding), 1 CTA/SM (208 KB smem).
// Grid = 16hb x 8qt x 8kq = 1024 (~7 balanced waves).
// Warp g1 owns key-pairs {i*16+g1}; K smem reads are warp-uniform broadcasts.
// Lane g2 owns query-pairs {p*32+g2}; conflict-free LDS.64.
// Tiles transposed [sd][pairs] u64, col-XOR-swizzled by q4 (cancels on read).
// No max-tracking (|score| <~ 75 -> exp cannot overflow).
// ---------------------------------------------------------------------------
__device__ __forceinline__ void ffma2(u64 &d, u64 a, u64 b){
    asm("fma.rn.f32x2 %0, %1, %2, %0;" : "+l"(d) : "l"(a), "l"(b));
}
__device__ __forceinline__ u64 swap_u64(u64 x){
    u32 lo = (u32)x, hi = (u32)(x >> 32);
    return ((u64)lo << 32) | (u64)hi;
}

#define QT_U64 (128*128)        /* [sd][128 qpairs] = 128 KB */
#define KT_U64 (128*64)         /* [sd][64  kpairs] =  64 KB */
#define SMEM2_BYTES (QT_U64*8 + KT_U64*8 + 16*256*4)   /* 212992 B */

__global__ __launch_bounds__(512,1) void mz_kernel(const float* __restrict__ q,
                                                   const float* __restrict__ k){
    extern __shared__ u64 sm[];
    u64*   Qt  = sm;                 float* Qtf = (float*)Qt;
    u64*   Kt  = sm + QT_U64;        float* Ktf = (float*)Kt;
    float* zs  = (float*)(sm + QT_U64 + KT_U64);   // [16 warps][256 queries]

    const int t  = threadIdx.x;
    const int hb = blockIdx.x >> 6;
    const int qt = (blockIdx.x >> 3) & 7;
    const int kq = blockIdx.x & 7;
    const int b  = hb >> 3, h = hb & 7;
    const float* Qg = q + ((size_t)(b*SEQ + qt*256))*DM + h*HD;
    const float* Kg = k + ((size_t)(b*SEQ + kq*256))*DM + h*HD;
    const int g2 = t & 31, g1 = t >> 5;

    // Q tile: load + swizzled transpose (256 queries x 128 dims), once.
#pragma unroll
    for (int mm = 0; mm < 16; ++mm){
        int f4 = mm*512 + t;
        int qr = f4 >> 5, c = f4 & 31;
        float4 v = ((const float4*)(Qg + (size_t)qr*DM))[c];
        int col = ((qr >> 1) ^ c)*2 + (qr & 1);
        Qtf[(4*c+0)*256 + col] = v.x;
        Qtf[(4*c+1)*256 + col] = v.y;
        Qtf[(4*c+2)*256 + col] = v.z;
        Qtf[(4*c+3)*256 + col] = v.w;
    }

    u64 accA[16], accB[16];
#pragma unroll
    for (int i = 0; i < 16; ++i){ accA[i] = 0; accB[i] = 0; }
    float z[8];
#pragma unroll
    for (int i = 0; i < 8; ++i) z[i] = 0.f;

    for (int kt = 0; kt < 2; ++kt){
        __syncthreads();
        // K tile: 128 keys x 128 dims, swizzled transpose.
#pragma unroll
        for (int mm = 0; mm < 8; ++mm){
            int f4 = mm*512 + t;
            int kr = f4 >> 5, c = f4 & 31;
            float4 v = ((const float4*)(Kg + (size_t)(kt*128 + kr)*DM))[c];
            int col = ((kr >> 1) ^ c)*2 + (kr & 1);
            Ktf[(4*c+0)*128 + col] = v.x;
            Ktf[(4*c+1)*128 + col] = v.y;
            Ktf[(4*c+2)*128 + col] = v.z;
            Ktf[(4*c+3)*128 + col] = v.w;
        }
        __syncthreads();

#pragma unroll 1
        for (int q4 = 0; q4 < 32; ++q4){        // sd = q4*4 + u
            const u64* kb = Kt + (size_t)q4*256;
            const u64* qb = Qt + (size_t)q4*512;
            u32 kc[4], qc[4];
#pragma unroll
            for (int i = 0; i < 4; ++i) kc[i] = (u32)((i*16 + g1) ^ q4);
#pragma unroll
            for (int p = 0; p < 4; ++p) qc[p] = (u32)((p*32 + g2) ^ q4);
#pragma unroll
            for (int u = 0; u < 4; ++u){
                u64 kk[4], ks[4], qq[4];
#pragma unroll
                for (int i = 0; i < 4; ++i) kk[i] = kb[u*64 + kc[i]];   // broadcast
#pragma unroll
                for (int p = 0; p < 4; ++p) qq[p] = qb[u*128 + qc[p]];
#pragma unroll
                for (int i = 0; i < 4; ++i) ks[i] = swap_u64(kk[i]);
#pragma unroll
                for (int p = 0; p < 4; ++p)
#pragma unroll
                    for (int i = 0; i < 4; ++i){
                        ffma2(accA[i*4+p], kk[i], qq[p]);
                        ffma2(accB[i*4+p], ks[i], qq[p]);
                    }
            }
        }

        // epilogue: z += sum(exp(score))
        // accA = (k_e*q_e, k_o*q_o); accB = (k_o*q_e, k_e*q_o)
#pragma unroll
        for (int p = 0; p < 4; ++p){
            float s0 = 0.f, s1 = 0.f;
#pragma unroll
            for (int i = 0; i < 4; ++i){
                u64 a = accA[i*4+p], bb = accB[i*4+p];
                s0 += __expf(__uint_as_float((u32)a));          // q even
                s0 += __expf(__uint_as_float((u32)bb));         // q even
                s1 += __expf(__uint_as_float((u32)(a >> 32)));  // q odd
                s1 += __expf(__uint_as_float((u32)(bb >> 32))); // q odd
                accA[i*4+p] = 0; accB[i*4+p] = 0;
            }
            z[2*p]   += s0;
            z[2*p+1] += s1;
        }
    }

    // cross-warp reduction over the 16 key-groups
    __syncthreads();
#pragma unroll
    for (int p = 0; p < 4; ++p){
        zs[g1*256 + 2*(p*32 + g2) + 0] = z[2*p];
        zs[g1*256 + 2*(p*32 + g2) + 1] = z[2*p+1];
    }
    __syncthreads();
    if (t < 256){
        float Zz = zs[t];
#pragma unroll
        for (int w = 1; w < 16; ++w) Zz += zs[w*256 + t];
        g_zpart[kq][hb*SEQ + qt*256 + t] = Zz;
    }
}

// ---------------------------------------------------------------------------
// Kernel 3: recompute 32 selected scores, renormalize with
// w_i = e^{s_i} / (sumE + 1e-5*Z), V gather, fused LayerNorm.
// ---------------------------------------------------------------------------
__global__ __launch_bounds__(256) void out_kernel(
    const float* __restrict__ q, const float* __restrict__ k, const float* __restrict__ v,
    const float* __restrict__ gamma, const float* __restrict__ beta, float* __restrict__ out)
{
    const int bs = blockIdx.x;
    const int b = bs >> 11, s = bs & (SEQ-1);
    const int t = threadIdx.x, h = t >> 5, lane = t & 31;
    const int row = (b*NH + h)*SEQ + s;
    __shared__ float se[8][32];
    __shared__ int   sk[8][32];
    __shared__ float sout[1024];
    __shared__ float sred[8][2];

    const float* qp = q + (size_t)(b*SEQ + s)*DM + h*HD;
    float4 q4 = ((const float4*)qp)[lane];
    float Zrow = 0.f;
#pragma unroll
    for (int j = 0; j < 8; ++j) Zrow += g_zpart[j][row];
    sk[h][lane] = g_topk[(size_t)row*TOPK + lane];
    __syncwarp();
    const float* kb = k + (size_t)b*SEQ*DM + h*HD;
    const float* vb = v + (size_t)b*SEQ*DM + h*HD;

    float sumE = 0.f;
#pragma unroll 4
    for (int j = 0; j < 32; ++j){
        int kj = sk[h][j];
        float4 k4 = ((const float4*)(kb + (size_t)kj*DM))[lane];
        float p = q4.x*k4.x + q4.y*k4.y + q4.z*k4.z + q4.w*k4.w;
#pragma unroll
        for (int o = 16; o; o >>= 1) p += __shfl_xor_sync(0xffffffffu, p, o);
        float e = __expf(p);
        sumE += e;
        if (lane == 0) se[h][j] = e;
    }
    __syncwarp();
    float rden = 1.f / (sumE + 1e-5f*Zrow);

    float4 acc = make_float4(0.f,0.f,0.f,0.f);
#pragma unroll 4
    for (int j = 0; j < 32; ++j){
        float w = se[h][j] * rden;
        int kj = sk[h][j];
        float4 v4 = ((const float4*)(vb + (size_t)kj*DM))[lane];
        acc.x += w*v4.x; acc.y += w*v4.y; acc.z += w*v4.z; acc.w += w*v4.w;
    }
    ((float4*)sout)[h*32 + lane] = acc;
    __syncthreads();

    float4 x = ((const float4*)sout)[t];
    float ps = x.x + x.y + x.z + x.w;
    float pq = x.x*x.x + x.y*x.y + x.z*x.z + x.w*x.w;
#pragma unroll
    for (int o = 16; o; o >>= 1){
        ps += __shfl_xor_sync(0xffffffffu, ps, o);
        pq += __shfl_xor_sync(0xffffffffu, pq, o);
    }
    if (lane == 0){ sred[h][0] = ps; sred[h][1] = pq; }
    __syncthreads();
    float Sm = 0.f, Sq = 0.f;
#pragma unroll
    for (int w = 0; w < 8; ++w){ Sm += sred[w][0]; Sq += sred[w][1]; }
    float mu  = Sm * (1.f/1024.f);
    float var = Sq * (1.f/1024.f) - mu*mu;
    float r   = rsqrtf(var + 1e-5f);
    float4 g4 = ((const float4*)gamma)[t];
    float4 b4 = ((const float4*)beta)[t];
    float4 y;
    y.x = (x.x-mu)*r*g4.x + b4.x;
    y.y = (x.y-mu)*r*g4.y + b4.y;
    y.z = (x.z-mu)*r*g4.z + b4.z;
    y.w = (x.w-mu)*r*g4.w + b4.w;
    ((float4*)(out + (size_t)bs*DM))[t] = y;
}

// ---------------------------------------------------------------------------
extern "C" void kernel_launch(void* const* d_in, const int* in_sizes, int n_in,
                              void* d_out, int out_size){
    const float* q     = (const float*)d_in[0];
    const float* k     = (const float*)d_in[1];
    const float* v     = (const float*)d_in[2];
    const float* aw    = (const float*)d_in[3];
    const float* gamma = (const float*)d_in[4];
    const float* beta  = (const float*)d_in[5];
    float* out = (float*)d_out;

    cudaFuncSetAttribute(mz_kernel, cudaFuncAttributeMaxDynamicSharedMemorySize, SMEM2_BYTES);

    topk_kernel<<<NROWS/8, 256>>>(aw);
    mz_kernel<<<16*8*8, 512, SMEM2_BYTES>>>(q, k);
    out_kernel<<<NB*SEQ, 256>>>(q, k, v, gamma, beta, out);
}

// round 12
// speedup vs baseline: 3.6719x; 1.0551x over previous
#include <cuda_runtime.h>

typedef unsigned long long u64;
typedef unsigned int u32;

#define SEQ   2048
#define DM    1024
#define NH    8
#define HD    128
#define NB    2
#define NROWS (NB*NH*SEQ)
#define TOPK  32

__device__ int   g_topk[NROWS*TOPK];
__device__ float g_zpart[8][NROWS];

__device__ __forceinline__ u32 fkey(float f){
    u32 b = __float_as_uint(f);
    return (b & 0x80000000u) ? ~b : (b | 0x80000000u);
}

// ---------------------------------------------------------------------------
// Kernel 2 (launched FIRST so ncu profiles it): partial Z per
// (hb, 256-query tile, 256-key slice) via dense-pair FFMA2.
// 256 threads, 1 CTA/SM, grid 16x8x8 = 1024 (~7 balanced waves).
// Warp-pair g1 = t>>4 owns 8 key-pairs {i*16+g1} (warp-uniform broadcast
// reads); g2 = t&15 owns 4 query-pairs {p*16+... see qc}. Tiles transposed
// [sd][pairs] u64, col-XOR-swizzled by q4 (cancels on read).
// No max-tracking (|score| <~ 75 -> exp cannot overflow fp32).
// ---------------------------------------------------------------------------
__device__ __forceinline__ void ffma2(u64 &d, u64 a, u64 b){
    asm("fma.rn.f32x2 %0, %1, %2, %0;" : "+l"(d) : "l"(a), "l"(b));
}
__device__ __forceinline__ u64 swap_u64(u64 x){
    u32 lo = (u32)x, hi = (u32)(x >> 32);
    return ((u64)lo << 32) | (u64)hi;
}

#define QT_U64 (128*128)        /* [sd][128 qpairs] = 128 KB */
#define KT_U64 (128*64)         /* [sd][64  kpairs] =  64 KB */
#define SMEM2_BYTES (QT_U64*8 + KT_U64*8 + 8*256*4)   /* 204800 B */

__global__ __launch_bounds__(256,1) void mz_kernel(const float* __restrict__ q,
                                                   const float* __restrict__ k){
    extern __shared__ u64 sm[];
    u64*   Qt  = sm;                 float* Qtf = (float*)Qt;
    u64*   Kt  = sm + QT_U64;        float* Ktf = (float*)Kt;
    float* zs  = (float*)(sm + QT_U64 + KT_U64);   // [8 warps][256 queries]

    const int t  = threadIdx.x;
    const int hb = blockIdx.x >> 6;
    const int qt = (blockIdx.x >> 3) & 7;
    const int kq = blockIdx.x & 7;
    const int b  = hb >> 3, h = hb & 7;
    const float* Qg = q + ((size_t)(b*SEQ + qt*256))*DM + h*HD;
    const float* Kg = k + ((size_t)(b*SEQ + kq*256))*DM + h*HD;
    const int g2 = t & 31, g1 = t >> 5;          // lane / warp (for transposes, zs)
    const int e2 = t & 15, e1 = t >> 4;          // compute-tile coords

    // Q tile: load + swizzled transpose (256 queries x 128 dims), once.
#pragma unroll
    for (int mm = 0; mm < 32; ++mm){
        int f4 = mm*256 + t;
        int qr = f4 >> 5, c = f4 & 31;
        float4 v = ((const float4*)(Qg + (size_t)qr*DM))[c];
        int col = ((qr >> 1) ^ c)*2 + (qr & 1);
        Qtf[(4*c+0)*256 + col] = v.x;
        Qtf[(4*c+1)*256 + col] = v.y;
        Qtf[(4*c+2)*256 + col] = v.z;
        Qtf[(4*c+3)*256 + col] = v.w;
    }

    u64 accA[32], accB[32];
#pragma unroll
    for (int i = 0; i < 32; ++i){ accA[i] = 0; accB[i] = 0; }
    float z[8];
#pragma unroll
    for (int i = 0; i < 8; ++i) z[i] = 0.f;

    float4 pf[8];

    for (int kt = 0; kt < 2; ++kt){
        __syncthreads();
        // K tile kt: 128 keys x 128 dims, swizzled transpose.
        // First half comes from the prefetch registers when kt==1.
#pragma unroll
        for (int mm = 0; mm < 8; ++mm){
            int f4 = mm*256 + t;
            int kr = f4 >> 5, c = f4 & 31;
            float4 v = (kt == 0) ? ((const float4*)(Kg + (size_t)kr*DM))[c] : pf[mm];
            int col = ((kr >> 1) ^ c)*2 + (kr & 1);
            Ktf[(4*c+0)*128 + col] = v.x;
            Ktf[(4*c+1)*128 + col] = v.y;
            Ktf[(4*c+2)*128 + col] = v.z;
            Ktf[(4*c+3)*128 + col] = v.w;
        }
#pragma unroll
        for (int mm = 8; mm < 16; ++mm){
            int f4 = mm*256 + t;
            int kr = f4 >> 5, c = f4 & 31;
            float4 v = ((const float4*)(Kg + (size_t)(kt*128 + kr)*DM))[c];
            int col = ((kr >> 1) ^ c)*2 + (kr & 1);
            Ktf[(4*c+0)*128 + col] = v.x;
            Ktf[(4*c+1)*128 + col] = v.y;
            Ktf[(4*c+2)*128 + col] = v.z;
            Ktf[(4*c+3)*128 + col] = v.w;
        }
        __syncthreads();

        if (kt == 0){
            // prefetch first half of K tile 1 during tile-0 compute
#pragma unroll
            for (int mm = 0; mm < 8; ++mm){
                int f4 = mm*256 + t;
                int kr = f4 >> 5, c = f4 & 31;
                pf[mm] = ((const float4*)(Kg + (size_t)(128 + kr)*DM))[c];
            }
        }

#pragma unroll 1
        for (int q4 = 0; q4 < 32; ++q4){        // sd = q4*4 + u
            const u64* kb = Kt + (size_t)q4*256;
            const u64* qb = Qt + (size_t)q4*512;
            u32 kc[8], qc[4];
#pragma unroll
            for (int i = 0; i < 8; ++i) kc[i] = (u32)((i*8 + e1) ^ q4);
#pragma unroll
            for (int p = 0; p < 4; ++p) qc[p] = (u32)((p*32 + e2*2 + (e2>>4)) ^ q4);
            // NOTE: e2*2 pattern removed; use original R10 mapping below instead
#pragma unroll
            for (int p = 0; p < 4; ++p) qc[p] = (u32)((p*32 + g2) ^ q4);
#pragma unroll
            for (int i = 0; i < 8; ++i) kc[i] = (u32)((i*8 + g1) ^ q4);
#pragma unroll
            for (int u = 0; u < 4; ++u){
                u64 kk[8], qq[4];
#pragma unroll
                for (int i = 0; i < 8; ++i) kk[i] = kb[u*64 + kc[i]];   // broadcast
#pragma unroll
                for (int p = 0; p < 4; ++p) qq[p] = qb[u*128 + qc[p]];
#pragma unroll
                for (int p = 0; p < 4; ++p){
                    u64 qs = swap_u64(qq[p]);
#pragma unroll
                    for (int i = 0; i < 8; ++i){
                        ffma2(accA[i*4+p], kk[i], qq[p]);
                        ffma2(accB[i*4+p], kk[i], qs);
                    }
                }
            }
        }

        // epilogue: z += sum(exp(score))
        // accA = (k_e*q_e, k_o*q_o); accB = (k_e*q_o, k_o*q_e)
#pragma unroll
        for (int p = 0; p < 4; ++p){
            float s0 = 0.f, s1 = 0.f;
#pragma unroll
            for (int i = 0; i < 8; ++i){
                u64 a = accA[i*4+p], bb = accB[i*4+p];
                s0 += __expf(__uint_as_float((u32)a));          // q even
                s0 += __expf(__uint_as_float((u32)(bb >> 32))); // q even
                s1 += __expf(__uint_as_float((u32)bb));         // q odd
                s1 += __expf(__uint_as_float((u32)(a >> 32)));  // q odd
                accA[i*4+p] = 0; accB[i*4+p] = 0;
            }
            z[2*p]   += s0;
            z[2*p+1] += s1;
        }
    }

    // reduce: key-groups 8 (g1 = warp), queries identified by (p, g2)
    __syncthreads();
#pragma unroll
    for (int p = 0; p < 4; ++p){
        zs[g1*256 + 2*(p*32 + g2) + 0] = z[2*p];
        zs[g1*256 + 2*(p*32 + g2) + 1] = z[2*p+1];
    }
    __syncthreads();
    if (t < 256){
        float Zz = zs[t];
#pragma unroll
        for (int w = 1; w < 8; ++w) Zz += zs[w*256 + t];
        g_zpart[kq][hb*SEQ + qt*256 + t] = Zz;
    }
}

// ---------------------------------------------------------------------------
// Kernel 1: warp-per-row exact top-32 (value desc, index asc).
// Threshold prefilter + REDUX.UMAX selection (32 rounds over split keys).
// Exact full-row fallback if filter yields <32 or >128 candidates.
// ---------------------------------------------------------------------------
#define TH0 1.9f
#define CANDMAX 128

__global__ __launch_bounds__(256) void topk_kernel(const float* __restrict__ aw){
    __shared__ u64 cand[8][CANDMAX];
    __shared__ u32 cnt[8];
    const int wid = threadIdx.x >> 5, lane = threadIdx.x & 31;
    const int row = blockIdx.x*8 + wid;
    const float* __restrict__ ar = aw + (size_t)row * SEQ;
    if (lane == 0) cnt[wid] = 0;
    __syncwarp();
#pragma unroll
    for (int it = 0; it < 16; ++it){
        float4 v = ((const float4*)ar)[it*32 + lane];
        float vs[4] = {v.x, v.y, v.z, v.w};
#pragma unroll
        for (int j = 0; j < 4; ++j){
            if (vs[j] >= TH0){
                u32 pos = atomicAdd(&cnt[wid], 1u);
                int idx = (it*32 + lane)*4 + j;
                if (pos < CANDMAX)
                    cand[wid][pos] = ((u64)fkey(vs[j]) << 32) | (u32)(SEQ-1-idx);
            }
        }
    }
    __syncwarp();
    u32 nc = cnt[wid];
    int* outp = g_topk + (size_t)row * TOPK;

    if (nc >= TOPK && nc <= CANDMAX){
        u32 khi[4], klo[4];
#pragma unroll
        for (int j = 0; j < 4; ++j){
            u32 p = lane + j*32;
            u64 c = (p < nc) ? cand[wid][p] : 0ull;
            khi[j] = (u32)(c >> 32);
            klo[j] = (u32)c;
        }
        for (int r = 0; r < TOPK; ++r){
            u32 loc = max(max(khi[0], khi[1]), max(khi[2], khi[3]));
            u32 wmax = __reduce_max_sync(0xffffffffu, loc);
            u32 ci = 0;
#pragma unroll
            for (int j = 0; j < 4; ++j) if (khi[j] == wmax) ci = max(ci, klo[j]);
            u32 wi = __reduce_max_sync(0xffffffffu, ci);
            if (lane == 0) outp[r] = (SEQ-1) - (int)wi;
#pragma unroll
            for (int j = 0; j < 4; ++j)
                if (khi[j] == wmax && klo[j] == wi) khi[j] = 0u;
        }
    } else {
        u64 W = ~0ull;
        for (int r = 0; r < TOPK; ++r){
            u64 loc = 0;
            for (int j = 0; j < 64; ++j){
                int idx = lane + j*32;
                u64 key = ((u64)fkey(ar[idx]) << 32) | (u32)(SEQ-1-idx);
                if (key < W && key > loc) loc = key;
            }
#pragma unroll
            for (int o = 16; o; o >>= 1){
                u64 w = __shfl_xor_sync(0xffffffffu, loc, o);
                loc = w > loc ? w : loc;
            }
            if (lane == 0) outp[r] = (SEQ-1) - (int)(u32)loc;
            W = loc;
        }
    }
}

// ---------------------------------------------------------------------------
// Kernel 3: recompute 32 selected scores, renormalize with
// w_i = e^{s_i} / (sumE + 1e-5*Z), V gather, fused LayerNorm.
// ---------------------------------------------------------------------------
__global__ __launch_bounds__(256) void out_kernel(
    const float* __restrict__ q, const float* __restrict__ k, const float* __restrict__ v,
    const float* __restrict__ gamma, const float* __restrict__ beta, float* __restrict__ out)
{
    const int bs = blockIdx.x;
    const int b = bs >> 11, s = bs & (SEQ-1);
    const int t = threadIdx.x, h = t >> 5, lane = t & 31;
    const int row = (b*NH + h)*SEQ + s;
    __shared__ float se[8][32];
    __shared__ int   sk[8][32];
    __shared__ float sout[1024];
    __shared__ float sred[8][2];

    const float* qp = q + (size_t)(b*SEQ + s)*DM + h*HD;
    float4 q4 = ((const float4*)qp)[lane];
    float Zrow = 0.f;
#pragma unroll
    for (int j = 0; j < 8; ++j) Zrow += g_zpart[j][row];
    sk[h][lane] = g_topk[(size_t)row*TOPK + lane];
    __syncwarp();
    const float* kb = k + (size_t)b*SEQ*DM + h*HD;
    const float* vb = v + (size_t)b*SEQ*DM + h*HD;

    float sumE = 0.f;
#pragma unroll 4
    for (int j = 0; j < 32; ++j){
        int kj = sk[h][j];
        float4 k4 = ((const float4*)(kb + (size_t)kj*DM))[lane];
        float p = q4.x*k4.x + q4.y*k4.y + q4.z*k4.z + q4.w*k4.w;
#pragma unroll
        for (int o = 16; o; o >>= 1) p += __shfl_xor_sync(0xffffffffu, p, o);
        float e = __expf(p);
        sumE += e;
        if (lane == 0) se[h][j] = e;
    }
    __syncwarp();
    float rden = 1.f / (sumE + 1e-5f*Zrow);

    float4 acc = make_float4(0.f,0.f,0.f,0.f);
#pragma unroll 4
    for (int j = 0; j < 32; ++j){
        float w = se[h][j] * rden;
        int kj = sk[h][j];
        float4 v4 = ((const float4*)(vb + (size_t)kj*DM))[lane];
        acc.x += w*v4.x; acc.y += w*v4.y; acc.z += w*v4.z; acc.w += w*v4.w;
    }
    ((float4*)sout)[h*32 + lane] = acc;
    __syncthreads();

    float4 x = ((const float4*)sout)[t];
    float ps = x.x + x.y + x.z + x.w;
    float pq = x.x*x.x + x.y*x.y + x.z*x.z + x.w*x.w;
#pragma unroll
    for (int o = 16; o; o >>= 1){
        ps += __shfl_xor_sync(0xffffffffu, ps, o);
        pq += __shfl_xor_sync(0xffffffffu, pq, o);
    }
    if (lane == 0){ sred[h][0] = ps; sred[h][1] = pq; }
    __syncthreads();
    float Sm = 0.f, Sq = 0.f;
#pragma unroll
    for (int w = 0; w < 8; ++w){ Sm += sred[w][0]; Sq += sred[w][1]; }
    float mu  = Sm * (1.f/1024.f);
    float var = Sq * (1.f/1024.f) - mu*mu;
    float r   = rsqrtf(var + 1e-5f);
    float4 g4 = ((const float4*)gamma)[t];
    float4 b4 = ((const float4*)beta)[t];
    float4 y;
    y.x = (x.x-mu)*r*g4.x + b4.x;
    y.y = (x.y-mu)*r*g4.y + b4.y;
    y.z = (x.z-mu)*r*g4.z + b4.z;
    y.w = (x.w-mu)*r*g4.w + b4.w;
    ((float4*)(out + (size_t)bs*DM))[t] = y;
}

// ---------------------------------------------------------------------------
extern "C" void kernel_launch(void* const* d_in, const int* in_sizes, int n_in,
                              void* d_out, int out_size){
    const float* q     = (const float*)d_in[0];
    const float* k     = (const float*)d_in[1];
    const float* v     = (const float*)d_in[2];
    const float* aw    = (const float*)d_in[3];
    const float* gamma = (const float*)d_in[4];
    const float* beta  = (const float*)d_in[5];
    float* out = (float*)d_out;

    cudaFuncSetAttribute(mz_kernel, cudaFuncAttributeMaxDynamicSharedMemorySize, SMEM2_BYTES);

    // mz first: independent of topk, and puts mz under the ncu capture window.
    mz_kernel<<<16*8*8, 256, SMEM2_BYTES>>>(q, k);
    topk_kernel<<<NROWS/8, 256>>>(aw);
    out_kernel<<<NB*SEQ, 256>>>(q, k, v, gamma, beta, out);
}

// round 13
// speedup vs baseline: 4.2972x; 1.1703x over previous
#include <cuda_runtime.h>

typedef unsigned long long u64;
typedef unsigned int u32;

#define SEQ   2048
#define DM    1024
#define NH    8
#define HD    128
#define NB    2
#define NROWS (NB*NH*SEQ)
#define TOPK  32

__device__ int   g_topk[NROWS*TOPK];
__device__ float g_zpart[4][NROWS];

__device__ __forceinline__ u32 fkey(float f){
    u32 b = __float_as_uint(f);
    return (b & 0x80000000u) ? ~b : (b | 0x80000000u);
}

// ===================== tf32 helpers =====================
__device__ __forceinline__ u32 cvt_tf32(float x){
    u32 r; asm("cvt.rna.tf32.f32 %0, %1;" : "=r"(r) : "f"(x)); return r;
}
__device__ __forceinline__ void mma_tf32(float* c, const u32* a, const u32* b){
    asm volatile("mma.sync.aligned.m16n8k8.row.col.f32.tf32.tf32.f32 "
        "{%0,%1,%2,%3}, {%4,%5,%6,%7}, {%8,%9}, {%0,%1,%2,%3};"
        : "+f"(c[0]), "+f"(c[1]), "+f"(c[2]), "+f"(c[3])
        : "r"(a[0]), "r"(a[1]), "r"(a[2]), "r"(a[3]), "r"(b[0]), "r"(b[1]));
}

// ---------------------------------------------------------------------------
// Kernel 2 (launched FIRST for ncu): partial Z per (hb, 128-q tile, 512-key
// slice) via tf32 mma.sync 3-pass split (hi*hi + hi*lo + lo*hi; lo*lo ~2^-22
// dropped). Q tile hi/lo staged once (pad-132 rows -> conflict-free fragment
// loads); K streamed in 64-key subtiles with register prefetch.
// Warp (wq,wk) owns 32q x 32k: per k8-slice 32 LDS.32 + 24 MMA.
// No max-tracking (|score| <~ 75, exp can't overflow fp32).
// ---------------------------------------------------------------------------
#define APAD 132
#define AL_OFF (128*APAD)
#define KH_OFF (2*128*APAD)
#define KL_OFF (2*128*APAD + 64*APAD)
#define ZR_OFF (2*128*APAD + 2*64*APAD)
#define SMEMZ_BYTES ((ZR_OFF + 256)*4)   /* 203776 B */

__global__ __launch_bounds__(256,1) void mz_kernel(const float* __restrict__ q,
                                                   const float* __restrict__ k){
    extern __shared__ u32 sm[];
    u32* Ah = sm;
    u32* Al = sm + AL_OFF;
    u32* Kh = sm + KH_OFF;
    u32* Kl = sm + KL_OFF;
    float* zr = (float*)(sm + ZR_OFF);

    const int t  = threadIdx.x;
    const int hb = blockIdx.x >> 6, qt = (blockIdx.x >> 2) & 15, kq = blockIdx.x & 3;
    const int b  = hb >> 3, h = hb & 7;
    const float* Qg = q + ((size_t)(b*SEQ + qt*128))*DM + h*HD;
    const float* Kg = k + ((size_t)(b*SEQ + kq*512))*DM + h*HD;

    const int lane = t & 31, wid = t >> 5;
    const int g = lane >> 2, tg = lane & 3;
    const int wq = wid >> 1, wk = wid & 1;

    // ---- Q tile -> smem (tf32 hi/lo), once ----
#pragma unroll
    for (int mm = 0; mm < 16; ++mm){
        int f4 = mm*256 + t;
        int row = f4 >> 5, c4 = (f4 & 31)*4;
        float4 v = *(const float4*)(Qg + (size_t)row*DM + c4);
        float xs[4] = {v.x, v.y, v.z, v.w};
        u32 hb4[4], lb4[4];
#pragma unroll
        for (int j = 0; j < 4; ++j){
            u32 hi = cvt_tf32(xs[j]);
            hb4[j] = hi;
            lb4[j] = cvt_tf32(xs[j] - __uint_as_float(hi));
        }
        *(uint4*)&Ah[row*APAD + c4] = make_uint4(hb4[0],hb4[1],hb4[2],hb4[3]);
        *(uint4*)&Al[row*APAD + c4] = make_uint4(lb4[0],lb4[1],lb4[2],lb4[3]);
    }

    float z[4] = {0.f, 0.f, 0.f, 0.f};
    float4 pf[8];

    // prefetch K subtile 0 (64 keys x 128 dims)
#pragma unroll
    for (int i = 0; i < 8; ++i){
        int f4 = i*256 + t;
        int row = f4 >> 5, c4 = (f4 & 31)*4;
        pf[i] = *(const float4*)(Kg + (size_t)row*DM + c4);
    }

    for (int s = 0; s < 8; ++s){
        // store prefetched subtile (cvt to hi/lo)
#pragma unroll
        for (int i = 0; i < 8; ++i){
            int f4 = i*256 + t;
            int row = f4 >> 5, c4 = (f4 & 31)*4;
            float xs[4] = {pf[i].x, pf[i].y, pf[i].z, pf[i].w};
            u32 hb4[4], lb4[4];
#pragma unroll
            for (int j = 0; j < 4; ++j){
                u32 hi = cvt_tf32(xs[j]);
                hb4[j] = hi;
                lb4[j] = cvt_tf32(xs[j] - __uint_as_float(hi));
            }
            *(uint4*)&Kh[row*APAD + c4] = make_uint4(hb4[0],hb4[1],hb4[2],hb4[3]);
            *(uint4*)&Kl[row*APAD + c4] = make_uint4(lb4[0],lb4[1],lb4[2],lb4[3]);
        }
        __syncthreads();

        // prefetch next subtile during compute
        if (s < 7){
#pragma unroll
            for (int i = 0; i < 8; ++i){
                int f4 = i*256 + t;
                int row = f4 >> 5, c4 = (f4 & 31)*4;
                pf[i] = *(const float4*)(Kg + (size_t)((s+1)*64 + row)*DM + c4);
            }
        }

        float c[2][4][4];
#pragma unroll
        for (int m = 0; m < 2; ++m)
#pragma unroll
            for (int n = 0; n < 4; ++n)
#pragma unroll
                for (int j = 0; j < 4; ++j) c[m][n][j] = 0.f;

#pragma unroll 2
        for (int slc = 0; slc < 16; ++slc){
            int d0 = slc*8;
            u32 ah[2][4], al[2][4], bh[4][2], bl[4][2];
#pragma unroll
            for (int m = 0; m < 2; ++m){
                int r0 = (32*wq + 16*m + g)*APAD + d0 + tg;
                ah[m][0] = Ah[r0];     ah[m][1] = Ah[r0 + 8*APAD];
                ah[m][2] = Ah[r0 + 4]; ah[m][3] = Ah[r0 + 8*APAD + 4];
                al[m][0] = Al[r0];     al[m][1] = Al[r0 + 8*APAD];
                al[m][2] = Al[r0 + 4]; al[m][3] = Al[r0 + 8*APAD + 4];
            }
#pragma unroll
            for (int n = 0; n < 4; ++n){
                int kk = (32*wk + 8*n + g)*APAD + d0 + tg;
                bh[n][0] = Kh[kk]; bh[n][1] = Kh[kk + 4];
                bl[n][0] = Kl[kk]; bl[n][1] = Kl[kk + 4];
            }
#pragma unroll
            for (int n = 0; n < 4; ++n)
#pragma unroll
                for (int m = 0; m < 2; ++m){
                    mma_tf32(c[m][n], ah[m], bh[n]);
                    mma_tf32(c[m][n], ah[m], bl[n]);
                    mma_tf32(c[m][n], al[m], bh[n]);
                }
        }

        // epilogue: z += exp(score); c rows: (m,g)->z[2m], (m,g+8)->z[2m+1]
#pragma unroll
        for (int m = 0; m < 2; ++m)
#pragma unroll
            for (int n = 0; n < 4; ++n){
                z[2*m]   += __expf(c[m][n][0]) + __expf(c[m][n][1]);
                z[2*m+1] += __expf(c[m][n][2]) + __expf(c[m][n][3]);
            }
        __syncthreads();   // K smem reused next subtile
    }

    // reduce across the 4 lanes of each group (they hold disjoint key-columns)
#pragma unroll
    for (int j = 0; j < 4; ++j){
        z[j] += __shfl_xor_sync(0xffffffffu, z[j], 1);
        z[j] += __shfl_xor_sync(0xffffffffu, z[j], 2);
    }
    if (tg == 0){
#pragma unroll
        for (int m = 0; m < 2; ++m){
            zr[wk*128 + 32*wq + 16*m + g]     = z[2*m];
            zr[wk*128 + 32*wq + 16*m + 8 + g] = z[2*m+1];
        }
    }
    __syncthreads();
    if (t < 128)
        g_zpart[kq][hb*SEQ + qt*128 + t] = zr[t] + zr[128 + t];
}

// ---------------------------------------------------------------------------
// Kernel 1: warp-per-row exact top-32 (value desc, index asc).
// Threshold prefilter + REDUX.UMAX selection; exact full-row fallback.
// ---------------------------------------------------------------------------
#define TH0 1.9f
#define CANDMAX 128

__global__ __launch_bounds__(256) void topk_kernel(const float* __restrict__ aw){
    __shared__ u64 cand[8][CANDMAX];
    __shared__ u32 cnt[8];
    const int wid = threadIdx.x >> 5, lane = threadIdx.x & 31;
    const int row = blockIdx.x*8 + wid;
    const float* __restrict__ ar = aw + (size_t)row * SEQ;
    if (lane == 0) cnt[wid] = 0;
    __syncwarp();
#pragma unroll
    for (int it = 0; it < 16; ++it){
        float4 v = ((const float4*)ar)[it*32 + lane];
        float vs[4] = {v.x, v.y, v.z, v.w};
#pragma unroll
        for (int j = 0; j < 4; ++j){
            if (vs[j] >= TH0){
                u32 pos = atomicAdd(&cnt[wid], 1u);
                int idx = (it*32 + lane)*4 + j;
                if (pos < CANDMAX)
                    cand[wid][pos] = ((u64)fkey(vs[j]) << 32) | (u32)(SEQ-1-idx);
            }
        }
    }
    __syncwarp();
    u32 nc = cnt[wid];
    int* outp = g_topk + (size_t)row * TOPK;

    if (nc >= TOPK && nc <= CANDMAX){
        u32 khi[4], klo[4];
#pragma unroll
        for (int j = 0; j < 4; ++j){
            u32 p = lane + j*32;
            u64 c = (p < nc) ? cand[wid][p] : 0ull;
            khi[j] = (u32)(c >> 32);
            klo[j] = (u32)c;
        }
        for (int r = 0; r < TOPK; ++r){
            u32 loc = max(max(khi[0], khi[1]), max(khi[2], khi[3]));
            u32 wmax = __reduce_max_sync(0xffffffffu, loc);
            u32 ci = 0;
#pragma unroll
            for (int j = 0; j < 4; ++j) if (khi[j] == wmax) ci = max(ci, klo[j]);
            u32 wi = __reduce_max_sync(0xffffffffu, ci);
            if (lane == 0) outp[r] = (SEQ-1) - (int)wi;
#pragma unroll
            for (int j = 0; j < 4; ++j)
                if (khi[j] == wmax && klo[j] == wi) khi[j] = 0u;
        }
    } else {
        u64 W = ~0ull;
        for (int r = 0; r < TOPK; ++r){
            u64 loc = 0;
            for (int j = 0; j < 64; ++j){
                int idx = lane + j*32;
                u64 key = ((u64)fkey(ar[idx]) << 32) | (u32)(SEQ-1-idx);
                if (key < W && key > loc) loc = key;
            }
#pragma unroll
            for (int o = 16; o; o >>= 1){
                u64 w = __shfl_xor_sync(0xffffffffu, loc, o);
                loc = w > loc ? w : loc;
            }
            if (lane == 0) outp[r] = (SEQ-1) - (int)(u32)loc;
            W = loc;
        }
    }
}

// ---------------------------------------------------------------------------
// Kernel 3: recompute 32 selected scores (full fp32), renormalize with
// w_i = e^{s_i} / (sumE + 1e-5*Z), V gather, fused LayerNorm.
// ---------------------------------------------------------------------------
__global__ __launch_bounds__(256) void out_kernel(
    const float* __restrict__ q, const float* __restrict__ k, const float* __restrict__ v,
    const float* __restrict__ gamma, const float* __restrict__ beta, float* __restrict__ out)
{
    const int bs = blockIdx.x;
    const int b = bs >> 11, s = bs & (SEQ-1);
    const int t = threadIdx.x, h = t >> 5, lane = t & 31;
    const int row = (b*NH + h)*SEQ + s;
    __shared__ float se[8][32];
    __shared__ int   sk[8][32];
    __shared__ float sout[1024];
    __shared__ float sred[8][2];

    const float* qp = q + (size_t)(b*SEQ + s)*DM + h*HD;
    float4 q4 = ((const float4*)qp)[lane];
    float Zrow = g_zpart[0][row] + g_zpart[1][row] + g_zpart[2][row] + g_zpart[3][row];
    sk[h][lane] = g_topk[(size_t)row*TOPK + lane];
    __syncwarp();
    const float* kb = k + (size_t)b*SEQ*DM + h*HD;
    const float* vb = v + (size_t)b*SEQ*DM + h*HD;

    float sumE = 0.f;
#pragma unroll 4
    for (int j = 0; j < 32; ++j){
        int kj = sk[h][j];
        float4 k4 = ((const float4*)(kb + (size_t)kj*DM))[lane];
        float p = q4.x*k4.x + q4.y*k4.y + q4.z*k4.z + q4.w*k4.w;
#pragma unroll
        for (int o = 16; o; o >>= 1) p += __shfl_xor_sync(0xffffffffu, p, o);
        float e = __expf(p);
        sumE += e;
        if (lane == 0) se[h][j] = e;
    }
    __syncwarp();
    float rden = 1.f / (sumE + 1e-5f*Zrow);

    float4 acc = make_float4(0.f,0.f,0.f,0.f);
#pragma unroll 4
    for (int j = 0; j < 32; ++j){
        float w = se[h][j] * rden;
        int kj = sk[h][j];
        float4 v4 = ((const float4*)(vb + (size_t)kj*DM))[lane];
        acc.x += w*v4.x; acc.y += w*v4.y; acc.z += w*v4.z; acc.w += w*v4.w;
    }
    ((float4*)sout)[h*32 + lane] = acc;
    __syncthreads();

    float4 x = ((const float4*)sout)[t];
    float ps = x.x + x.y + x.z + x.w;
    float pq = x.x*x.x + x.y*x.y + x.z*x.z + x.w*x.w;
#pragma unroll
    for (int o = 16; o; o >>= 1){
        ps += __shfl_xor_sync(0xffffffffu, ps, o);
        pq += __shfl_xor_sync(0xffffffffu, pq, o);
    }
    if (lane == 0){ sred[h][0] = ps; sred[h][1] = pq; }
    __syncthreads();
    float Sm = 0.f, Sq = 0.f;
#pragma unroll
    for (int w = 0; w < 8; ++w){ Sm += sred[w][0]; Sq += sred[w][1]; }
    float mu  = Sm * (1.f/1024.f);
    float var = Sq * (1.f/1024.f) - mu*mu;
    float r   = rsqrtf(var + 1e-5f);
    float4 g4 = ((const float4*)gamma)[t];
    float4 b4 = ((const float4*)beta)[t];
    float4 y;
    y.x = (x.x-mu)*r*g4.x + b4.x;
    y.y = (x.y-mu)*r*g4.y + b4.y;
    y.z = (x.z-mu)*r*g4.z + b4.z;
    y.w = (x.w-mu)*r*g4.w + b4.w;
    ((float4*)(out + (size_t)bs*DM))[t] = y;
}

// ---------------------------------------------------------------------------
extern "C" void kernel_launch(void* const* d_in, const int* in_sizes, int n_in,
                              void* d_out, int out_size){
    const float* q     = (const float*)d_in[0];
    const float* k     = (const float*)d_in[1];
    const float* v     = (const float*)d_in[2];
    const float* aw    = (const float*)d_in[3];
    const float* gamma = (const float*)d_in[4];
    const float* beta  = (const float*)d_in[5];
    float* out = (float*)d_out;

    cudaFuncSetAttribute(mz_kernel, cudaFuncAttributeMaxDynamicSharedMemorySize, SMEMZ_BYTES);

    // mz first: independent of topk, and lands under the ncu capture window.
    mz_kernel<<<16*16*4, 256, SMEMZ_BYTES>>>(q, k);
    topk_kernel<<<NROWS/8, 256>>>(aw);
    out_kernel<<<NB*SEQ, 256>>>(q, k, v, gamma, beta, out);
}